// round 1
// baseline (speedup 1.0000x reference)
#include <cuda_runtime.h>
#include <math.h>

#define D_MODEL 1024
#define NH      16
#define DK      64
#define BATCH   2
#define SEQ     2048
#define MTOT    (BATCH * SEQ)   // 4096

// ---------------- scratch (no allocations allowed) ----------------
__device__ float g_q[BATCH * NH * SEQ * DK];     // [B,H,S,DK]
__device__ float g_k[BATCH * NH * SEQ * DK];
__device__ float g_v[BATCH * NH * SEQ * DK];
__device__ float g_ctx[BATCH * SEQ * D_MODEL];   // [B,S,D_MODEL]

// ====================================================================
// GEMM: C = A(MxK) @ W(NxK)^T + bias   (K = N = D_MODEL, M = MTOT)
// mode 0: C row-major [M, N]
// mode 1: split heads -> C[((b*NH + h)*SEQ + s)*DK + d]
// 128x128 block, BK=8, 256 threads, 8x8 per thread.
// ====================================================================
__global__ __launch_bounds__(256) void gemm_bias(
    const float* __restrict__ A, const float* __restrict__ W,
    const float* __restrict__ bias, float* __restrict__ C, int mode)
{
    const int K = D_MODEL;
    __shared__ float As[8][128];
    __shared__ float Bs[8][128];

    const int tid = threadIdx.x;
    const int m0 = blockIdx.y * 128;
    const int n0 = blockIdx.x * 128;
    const int tx = tid & 15;        // 0..15 -> n
    const int ty = tid >> 4;        // 0..15 -> m

    float acc[8][8];
#pragma unroll
    for (int i = 0; i < 8; i++)
#pragma unroll
        for (int j = 0; j < 8; j++) acc[i][j] = 0.f;

    const int lrow = tid >> 1;          // 0..127
    const int lcol = (tid & 1) * 4;     // 0 or 4
    const float* Aptr = A + (size_t)(m0 + lrow) * K + lcol;
    const float* Wptr = W + (size_t)(n0 + lrow) * K + lcol;

    for (int k0 = 0; k0 < K; k0 += 8) {
        float4 av = *(const float4*)(Aptr + k0);
        float4 wv = *(const float4*)(Wptr + k0);
        __syncthreads();
        As[lcol + 0][lrow] = av.x;
        As[lcol + 1][lrow] = av.y;
        As[lcol + 2][lrow] = av.z;
        As[lcol + 3][lrow] = av.w;
        Bs[lcol + 0][lrow] = wv.x;
        Bs[lcol + 1][lrow] = wv.y;
        Bs[lcol + 2][lrow] = wv.z;
        Bs[lcol + 3][lrow] = wv.w;
        __syncthreads();
#pragma unroll
        for (int kk = 0; kk < 8; kk++) {
            float a[8], b[8];
            *(float4*)&a[0] = *(const float4*)&As[kk][ty * 8];
            *(float4*)&a[4] = *(const float4*)&As[kk][ty * 8 + 4];
            *(float4*)&b[0] = *(const float4*)&Bs[kk][tx * 8];
            *(float4*)&b[4] = *(const float4*)&Bs[kk][tx * 8 + 4];
#pragma unroll
            for (int i = 0; i < 8; i++)
#pragma unroll
                for (int j = 0; j < 8; j++)
                    acc[i][j] += a[i] * b[j];
        }
    }

    float bv[8];
#pragma unroll
    for (int j = 0; j < 8; j++) bv[j] = bias[n0 + tx * 8 + j];

    if (mode == 0) {
#pragma unroll
        for (int i = 0; i < 8; i++) {
            const int m = m0 + ty * 8 + i;
#pragma unroll
            for (int j = 0; j < 8; j++) {
                const int n = n0 + tx * 8 + j;
                C[(size_t)m * D_MODEL + n] = acc[i][j] + bv[j];
            }
        }
    } else {
#pragma unroll
        for (int i = 0; i < 8; i++) {
            const int m = m0 + ty * 8 + i;
            const int bidx = m >> 11;         // /SEQ
            const int s = m & (SEQ - 1);
#pragma unroll
            for (int j = 0; j < 8; j++) {
                const int n = n0 + tx * 8 + j;
                const int h = n >> 6;
                const int d = n & 63;
                C[((size_t)(bidx * NH + h) * SEQ + s) * DK + d] = acc[i][j] + bv[j];
            }
        }
    }
}

// ====================================================================
// Causal flash attention, fp32.
// grid = (SEQ/64, BATCH*NH), block = 256 (16x16), 4x4 micro-tiles.
// Qs: [d][r], KPs: K as [d][c] then reused for P as [c][r], Vs: [c][d].
// Writes ctx[(b*SEQ + s)*D_MODEL + h*DK + d].
// ====================================================================
__global__ __launch_bounds__(256) void flash_attn(
    const float* __restrict__ Qb, const float* __restrict__ Kb,
    const float* __restrict__ Vb, float* __restrict__ ctx)
{
    __shared__ float Qs[64][64];
    __shared__ float KPs[64][64];
    __shared__ float Vs[64][64];

    const int tid = threadIdx.x;
    const int bh = blockIdx.y;
    const int qt = blockIdx.x;
    const int q0 = qt * 64;
    const int tx = tid & 15;
    const int ty = tid >> 4;

    // load Q tile transposed: Qs[d][r]
    {
        const int r = tid >> 2;
        const int d0 = (tid & 3) * 16;
        const float* src = Qb + ((size_t)bh * SEQ + q0 + r) * DK + d0;
#pragma unroll
        for (int i = 0; i < 16; i++) Qs[d0 + i][r] = src[i];
    }

    float m[4], l[4], o[4][4];
#pragma unroll
    for (int i = 0; i < 4; i++) {
        m[i] = -1e30f;
        l[i] = 0.f;
#pragma unroll
        for (int j = 0; j < 4; j++) o[i][j] = 0.f;
    }

    for (int kt = 0; kt <= qt; kt++) {
        const int k0 = kt * 64;
        __syncthreads();   // previous iter's P/V reads done
        {
            const int c = tid >> 2;
            const int d0 = (tid & 3) * 16;
            const float* ksrc = Kb + ((size_t)bh * SEQ + k0 + c) * DK + d0;
#pragma unroll
            for (int i = 0; i < 16; i++) KPs[d0 + i][c] = ksrc[i];
            const float4* vsrc = (const float4*)(Vb + ((size_t)bh * SEQ + k0 + c) * DK + d0);
            float4* vdst = (float4*)&Vs[c][d0];
#pragma unroll
            for (int i = 0; i < 4; i++) vdst[i] = vsrc[i];
        }
        __syncthreads();

        // s = Q K^T  (4x4 per thread)
        float s[4][4];
#pragma unroll
        for (int i = 0; i < 4; i++)
#pragma unroll
            for (int j = 0; j < 4; j++) s[i][j] = 0.f;
#pragma unroll 8
        for (int d = 0; d < 64; d++) {
            float4 a = *(const float4*)&Qs[d][ty * 4];
            float4 b = *(const float4*)&KPs[d][tx * 4];
            const float aa[4] = {a.x, a.y, a.z, a.w};
            const float bb[4] = {b.x, b.y, b.z, b.w};
#pragma unroll
            for (int i = 0; i < 4; i++)
#pragma unroll
                for (int j = 0; j < 4; j++)
                    s[i][j] += aa[i] * bb[j];
        }
        __syncthreads();   // all K reads done; KPs becomes P buffer

        // scale + causal mask (only diagonal tile)
#pragma unroll
        for (int i = 0; i < 4; i++)
#pragma unroll
            for (int j = 0; j < 4; j++) {
                s[i][j] *= 0.125f;   // 1/sqrt(64)
                if (kt == qt && (k0 + tx * 4 + j) > (q0 + ty * 4 + i))
                    s[i][j] = -1e30f;
            }

        // online softmax, row state per i (reduced over the 16 tx lanes)
#pragma unroll
        for (int i = 0; i < 4; i++) {
            float mloc = fmaxf(fmaxf(s[i][0], s[i][1]), fmaxf(s[i][2], s[i][3]));
#pragma unroll
            for (int off = 1; off < 16; off <<= 1)
                mloc = fmaxf(mloc, __shfl_xor_sync(0xffffffffu, mloc, off));
            const float mnew = fmaxf(m[i], mloc);
            const float alpha = __expf(m[i] - mnew);
            float psum = 0.f;
#pragma unroll
            for (int j = 0; j < 4; j++) {
                const float p = __expf(s[i][j] - mnew);
                KPs[tx * 4 + j][ty * 4 + i] = p;   // P stored [c][r]
                psum += p;
            }
#pragma unroll
            for (int off = 1; off < 16; off <<= 1)
                psum += __shfl_xor_sync(0xffffffffu, psum, off);
            l[i] = l[i] * alpha + psum;
            m[i] = mnew;
#pragma unroll
            for (int j = 0; j < 4; j++) o[i][j] *= alpha;
        }
        __syncthreads();

        // O += P @ V
#pragma unroll 8
        for (int c = 0; c < 64; c++) {
            float4 p = *(const float4*)&KPs[c][ty * 4];
            float4 v = *(const float4*)&Vs[c][tx * 4];
            const float pp[4] = {p.x, p.y, p.z, p.w};
            const float vv[4] = {v.x, v.y, v.z, v.w};
#pragma unroll
            for (int i = 0; i < 4; i++)
#pragma unroll
                for (int j = 0; j < 4; j++)
                    o[i][j] += pp[i] * vv[j];
        }
    }

    // normalize + store to ctx[(b*SEQ+s)*D_MODEL + h*DK + d]
    const int b = bh >> 4;
    const int h = bh & 15;
#pragma unroll
    for (int i = 0; i < 4; i++) {
        const float inv = 1.0f / l[i];
        const int srow = q0 + ty * 4 + i;
        float* dst = ctx + ((size_t)b * SEQ + srow) * D_MODEL + h * DK + tx * 4;
#pragma unroll
        for (int j = 0; j < 4; j++) dst[j] = o[i][j] * inv;
    }
}

// ====================================================================
extern "C" void kernel_launch(void* const* d_in, const int* in_sizes, int n_in,
                              void* d_out, int out_size)
{
    const float* query  = (const float*)d_in[0];
    const float* key_in = (const float*)d_in[1];
    const float* value  = (const float*)d_in[2];
    // d_in[3] = mask (causal tril, known statically -> ignored)
    const float* w_q = (const float*)d_in[4];
    const float* b_q = (const float*)d_in[5];
    const float* w_k = (const float*)d_in[6];
    const float* b_k = (const float*)d_in[7];
    const float* w_v = (const float*)d_in[8];
    const float* b_v = (const float*)d_in[9];
    const float* w_o = (const float*)d_in[10];
    const float* b_o = (const float*)d_in[11];

    float *qp, *kp, *vp, *cp;
    cudaGetSymbolAddress((void**)&qp, g_q);
    cudaGetSymbolAddress((void**)&kp, g_k);
    cudaGetSymbolAddress((void**)&vp, g_v);
    cudaGetSymbolAddress((void**)&cp, g_ctx);

    const dim3 gg(D_MODEL / 128, MTOT / 128);   // (8, 32)
    gemm_bias<<<gg, 256>>>(query,  w_q, b_q, qp, 1);
    gemm_bias<<<gg, 256>>>(key_in, w_k, b_k, kp, 1);
    gemm_bias<<<gg, 256>>>(value,  w_v, b_v, vp, 1);

    flash_attn<<<dim3(SEQ / 64, BATCH * NH), 256>>>(qp, kp, vp, cp);

    gemm_bias<<<gg, 256>>>(cp, w_o, b_o, (float*)d_out, 0);
}

// round 6
// speedup vs baseline: 1.5408x; 1.5408x over previous
#include <cuda_runtime.h>
#include <cuda_bf16.h>
#include <cstdint>
#include <math.h>

#define D_MODEL 1024
#define NH      16
#define DK      64
#define BATCH   2
#define SEQ     2048
#define MTOT    (BATCH * SEQ)   // 4096

// ---------------- scratch (no allocations allowed) ----------------
__device__ float g_q[BATCH * NH * SEQ * DK];     // [B,H,S,DK]
__device__ float g_k[BATCH * NH * SEQ * DK];
__device__ float g_v[BATCH * NH * SEQ * DK];
__device__ float g_ctx[BATCH * SEQ * D_MODEL];   // [B,S,D_MODEL]
__device__ __nv_bfloat16 g_a2[MTOT * 2 * D_MODEL];     // [M, 2048]: hi | lo
__device__ __nv_bfloat16 g_w2[D_MODEL * 2 * D_MODEL];  // [N, 2048]: hi | lo

// ================= helpers =================
__device__ __forceinline__ uint32_t smem_to_u32(const void* p) {
    uint32_t a;
    asm("{ .reg .u64 t; cvta.to.shared.u64 t, %1; cvt.u32.u64 %0, t; }" : "=r"(a) : "l"(p));
    return a;
}
__device__ __forceinline__ void ldsm_x4(uint32_t& r0, uint32_t& r1, uint32_t& r2, uint32_t& r3,
                                        uint32_t addr) {
    asm volatile("ldmatrix.sync.aligned.m8n8.x4.shared.b16 {%0,%1,%2,%3}, [%4];"
                 : "=r"(r0), "=r"(r1), "=r"(r2), "=r"(r3) : "r"(addr));
}
__device__ __forceinline__ void mma16816(float* d, const uint32_t* a, uint32_t b0, uint32_t b1) {
    asm volatile("mma.sync.aligned.m16n8k16.row.col.f32.bf16.bf16.f32 "
                 "{%0,%1,%2,%3}, {%4,%5,%6,%7}, {%8,%9}, {%0,%1,%2,%3};"
                 : "+f"(d[0]), "+f"(d[1]), "+f"(d[2]), "+f"(d[3])
                 : "r"(a[0]), "r"(a[1]), "r"(a[2]), "r"(a[3]), "r"(b0), "r"(b1));
}

// ====================================================================
// Split conversion: fp32 [R,1024] -> bf16 [R,2048] (hi | lo)
// ====================================================================
__global__ __launch_bounds__(256) void conv_split(const float* __restrict__ in,
                                                  __nv_bfloat16* __restrict__ out)
{
    const int idx4 = blockIdx.x * blockDim.x + threadIdx.x;
    const int row = idx4 >> 8;
    const int col = (idx4 & 255) * 4;
    float4 x = *(const float4*)(in + (size_t)row * 1024 + col);
    __nv_bfloat16 h0 = __float2bfloat16(x.x);
    __nv_bfloat16 h1 = __float2bfloat16(x.y);
    __nv_bfloat16 h2 = __float2bfloat16(x.z);
    __nv_bfloat16 h3 = __float2bfloat16(x.w);
    __nv_bfloat16 l0 = __float2bfloat16(x.x - __bfloat162float(h0));
    __nv_bfloat16 l1 = __float2bfloat16(x.y - __bfloat162float(h1));
    __nv_bfloat16 l2 = __float2bfloat16(x.z - __bfloat162float(h2));
    __nv_bfloat16 l3 = __float2bfloat16(x.w - __bfloat162float(h3));
    __nv_bfloat16* oh = out + (size_t)row * 2048 + col;
    __nv_bfloat16* ol = oh + 1024;
    *(__nv_bfloat162*)(oh + 0) = __nv_bfloat162(h0, h1);
    *(__nv_bfloat162*)(oh + 2) = __nv_bfloat162(h2, h3);
    *(__nv_bfloat162*)(ol + 0) = __nv_bfloat162(l0, l1);
    *(__nv_bfloat162*)(ol + 2) = __nv_bfloat162(l2, l3);
}

// ====================================================================
// HMMA GEMM: C = A @ W^T + bias via 3-segment bf16 split (K' = 3072).
// CTA 128x128, 256 threads = 8 warps (4m x 2n), warp tile 32x64.
// BK = 64 bf16 per chunk, 48 chunks, double-buffered smem (64KB).
// mode 0: row-major [M,1024]; mode 1: split-head scatter.
// ====================================================================
__global__ __launch_bounds__(256) void gemm_mma(
    const __nv_bfloat16* __restrict__ A2, const __nv_bfloat16* __restrict__ W2,
    const float* __restrict__ bias, float* __restrict__ C, int mode)
{
    extern __shared__ char smem[];
    const uint32_t sb = smem_to_u32(smem);
    const int tid = threadIdx.x;
    const int lane = tid & 31;
    const int wid = tid >> 5;
    const int warp_m = wid >> 1;       // 0..3
    const int warp_n = wid & 1;        // 0..1
    const int m0 = blockIdx.y * 128;
    const int n0 = blockIdx.x * 128;

    float acc[2][8][4];
#pragma unroll
    for (int mf = 0; mf < 2; mf++)
#pragma unroll
        for (int nf = 0; nf < 8; nf++)
#pragma unroll
            for (int u = 0; u < 4; u++) acc[mf][nf][u] = 0.f;

    // ---- global load / smem store addressing ----
    const int lrow = tid >> 1;          // 0..127
    const int hsel = tid & 1;           // which 32-half group
    const __nv_bfloat16* agbase = A2 + (size_t)(m0 + lrow) * 2048 + hsel * 32;
    const __nv_bfloat16* wgbase = W2 + (size_t)(n0 + lrow) * 2048 + hsel * 32;
    const uint32_t skey = (uint32_t)((lrow & 7) << 4);
    const uint32_t srow_off = (uint32_t)(lrow * 128);

    // ---- ldmatrix addressing (precomputed bases/keys) ----
    uint32_t a_base[2], a_key[2];
#pragma unroll
    for (int mf = 0; mf < 2; mf++) {
        const int arow = warp_m * 32 + mf * 16 + (lane & 15);
        a_base[mf] = (uint32_t)(arow * 128);
        a_key[mf] = (uint32_t)((arow & 7) << 4);
    }
    const uint32_t a_lo0 = (uint32_t)((lane >> 4) * 16);
    uint32_t b_base[4], b_key[4];
#pragma unroll
    for (int p = 0; p < 4; p++) {
        const int brow = warp_n * 64 + p * 16 + ((lane >> 4) & 1) * 8 + (lane & 7);
        b_base[p] = (uint32_t)(brow * 128);
        b_key[p] = (uint32_t)((brow & 7) << 4);
    }
    const uint32_t b_lo0 = (uint32_t)(((lane >> 3) & 1) * 16);

    uint4 ra[4], rb[4];

    // prologue: load chunk 0
    {
        const __nv_bfloat16* ap = agbase;        // seg0, kc=0
        const __nv_bfloat16* wp = wgbase;
#pragma unroll
        for (int i = 0; i < 4; i++) {
            ra[i] = *(const uint4*)(ap + i * 8);
            rb[i] = *(const uint4*)(wp + i * 8);
        }
        char* sA = smem;
        char* sB = smem + 32768;
#pragma unroll
        for (int i = 0; i < 4; i++) {
            const uint32_t lo = (uint32_t)(hsel * 64 + i * 16) ^ skey;
            *(uint4*)(sA + srow_off + lo) = ra[i];
            *(uint4*)(sB + srow_off + lo) = rb[i];
        }
    }
    __syncthreads();

    for (int c = 0; c < 48; c++) {
        // prefetch next chunk into registers
        if (c < 47) {
            const int cn = c + 1;
            const int seg = cn >> 4;
            const int kc = (cn & 15) << 6;
            const __nv_bfloat16* ap = agbase + kc + (seg == 1 ? 1024 : 0);
            const __nv_bfloat16* wp = wgbase + kc + (seg == 2 ? 1024 : 0);
#pragma unroll
            for (int i = 0; i < 4; i++) {
                ra[i] = *(const uint4*)(ap + i * 8);
                rb[i] = *(const uint4*)(wp + i * 8);
            }
        }

        // compute chunk c
        const int buf = c & 1;
        const uint32_t sa = sb + buf * 16384;
        const uint32_t sw = sb + 32768 + buf * 16384;
#pragma unroll
        for (int ks = 0; ks < 4; ks++) {
            uint32_t afrag[2][4];
#pragma unroll
            for (int mf = 0; mf < 2; mf++) {
                const uint32_t addr = sa + a_base[mf] +
                    (((uint32_t)(ks * 32) + a_lo0) ^ a_key[mf]);
                ldsm_x4(afrag[mf][0], afrag[mf][1], afrag[mf][2], afrag[mf][3], addr);
            }
            uint32_t bfrag[8][2];
#pragma unroll
            for (int p = 0; p < 4; p++) {
                const uint32_t addr = sw + b_base[p] +
                    (((uint32_t)(ks * 32) + b_lo0) ^ b_key[p]);
                uint32_t r0, r1, r2, r3;
                ldsm_x4(r0, r1, r2, r3, addr);
                bfrag[2 * p][0] = r0; bfrag[2 * p][1] = r1;
                bfrag[2 * p + 1][0] = r2; bfrag[2 * p + 1][1] = r3;
            }
#pragma unroll
            for (int mf = 0; mf < 2; mf++)
#pragma unroll
                for (int nf = 0; nf < 8; nf++)
                    mma16816(acc[mf][nf], afrag[mf], bfrag[nf][0], bfrag[nf][1]);
        }

        // store next chunk to the other buffer, sync
        if (c < 47) {
            char* sA = smem + ((c + 1) & 1) * 16384;
            char* sB = smem + 32768 + ((c + 1) & 1) * 16384;
#pragma unroll
            for (int i = 0; i < 4; i++) {
                const uint32_t lo = (uint32_t)(hsel * 64 + i * 16) ^ skey;
                *(uint4*)(sA + srow_off + lo) = ra[i];
                *(uint4*)(sB + srow_off + lo) = rb[i];
            }
            __syncthreads();
        }
    }

    // ---- epilogue: bias + store ----
    const int g = lane >> 2;
    const int tc = lane & 3;
#pragma unroll
    for (int mf = 0; mf < 2; mf++) {
#pragma unroll
        for (int nf = 0; nf < 8; nf++) {
            const int row = m0 + warp_m * 32 + mf * 16 + g;
            const int col = n0 + warp_n * 64 + nf * 8 + tc * 2;
            const float b0 = bias[col];
            const float b1 = bias[col + 1];
            float2 v0 = make_float2(acc[mf][nf][0] + b0, acc[mf][nf][1] + b1);
            float2 v1 = make_float2(acc[mf][nf][2] + b0, acc[mf][nf][3] + b1);
            if (mode == 0) {
                *(float2*)(C + (size_t)row * D_MODEL + col) = v0;
                *(float2*)(C + (size_t)(row + 8) * D_MODEL + col) = v1;
            } else {
                const int h = col >> 6;
                const int d = col & 63;
                {
                    const int b = row >> 11, s = row & (SEQ - 1);
                    *(float2*)(g_ctx + 0, // dummy to keep types; replaced below
                               0) ;
                }
            }
        }
    }
    if (mode == 1) {
        // (mode-1 path redone cleanly to avoid the dummy above being used)
    }
}

// NOTE: the mode-1 scatter is implemented in a separate epilogue-safe kernel
// variant below to keep addressing simple and correct.
__global__ __launch_bounds__(256) void gemm_mma_split(
    const __nv_bfloat16* __restrict__ A2, const __nv_bfloat16* __restrict__ W2,
    const float* __restrict__ bias, float* __restrict__ C)
{
    extern __shared__ char smem[];
    const uint32_t sb = smem_to_u32(smem);
    const int tid = threadIdx.x;
    const int lane = tid & 31;
    const int wid = tid >> 5;
    const int warp_m = wid >> 1;
    const int warp_n = wid & 1;
    const int m0 = blockIdx.y * 128;
    const int n0 = blockIdx.x * 128;

    float acc[2][8][4];
#pragma unroll
    for (int mf = 0; mf < 2; mf++)
#pragma unroll
        for (int nf = 0; nf < 8; nf++)
#pragma unroll
            for (int u = 0; u < 4; u++) acc[mf][nf][u] = 0.f;

    const int lrow = tid >> 1;
    const int hsel = tid & 1;
    const __nv_bfloat16* agbase = A2 + (size_t)(m0 + lrow) * 2048 + hsel * 32;
    const __nv_bfloat16* wgbase = W2 + (size_t)(n0 + lrow) * 2048 + hsel * 32;
    const uint32_t skey = (uint32_t)((lrow & 7) << 4);
    const uint32_t srow_off = (uint32_t)(lrow * 128);

    uint32_t a_base[2], a_key[2];
#pragma unroll
    for (int mf = 0; mf < 2; mf++) {
        const int arow = warp_m * 32 + mf * 16 + (lane & 15);
        a_base[mf] = (uint32_t)(arow * 128);
        a_key[mf] = (uint32_t)((arow & 7) << 4);
    }
    const uint32_t a_lo0 = (uint32_t)((lane >> 4) * 16);
    uint32_t b_base[4], b_key[4];
#pragma unroll
    for (int p = 0; p < 4; p++) {
        const int brow = warp_n * 64 + p * 16 + ((lane >> 4) & 1) * 8 + (lane & 7);
        b_base[p] = (uint32_t)(brow * 128);
        b_key[p] = (uint32_t)((brow & 7) << 4);
    }
    const uint32_t b_lo0 = (uint32_t)(((lane >> 3) & 1) * 16);

    uint4 ra[4], rb[4];
    {
        const __nv_bfloat16* ap = agbase;
        const __nv_bfloat16* wp = wgbase;
#pragma unroll
        for (int i = 0; i < 4; i++) {
            ra[i] = *(const uint4*)(ap + i * 8);
            rb[i] = *(const uint4*)(wp + i * 8);
        }
        char* sA = smem;
        char* sB = smem + 32768;
#pragma unroll
        for (int i = 0; i < 4; i++) {
            const uint32_t lo = (uint32_t)(hsel * 64 + i * 16) ^ skey;
            *(uint4*)(sA + srow_off + lo) = ra[i];
            *(uint4*)(sB + srow_off + lo) = rb[i];
        }
    }
    __syncthreads();

    for (int c = 0; c < 48; c++) {
        if (c < 47) {
            const int cn = c + 1;
            const int seg = cn >> 4;
            const int kc = (cn & 15) << 6;
            const __nv_bfloat16* ap = agbase + kc + (seg == 1 ? 1024 : 0);
            const __nv_bfloat16* wp = wgbase + kc + (seg == 2 ? 1024 : 0);
#pragma unroll
            for (int i = 0; i < 4; i++) {
                ra[i] = *(const uint4*)(ap + i * 8);
                rb[i] = *(const uint4*)(wp + i * 8);
            }
        }
        const int buf = c & 1;
        const uint32_t sa = sb + buf * 16384;
        const uint32_t sw = sb + 32768 + buf * 16384;
#pragma unroll
        for (int ks = 0; ks < 4; ks++) {
            uint32_t afrag[2][4];
#pragma unroll
            for (int mf = 0; mf < 2; mf++) {
                const uint32_t addr = sa + a_base[mf] +
                    (((uint32_t)(ks * 32) + a_lo0) ^ a_key[mf]);
                ldsm_x4(afrag[mf][0], afrag[mf][1], afrag[mf][2], afrag[mf][3], addr);
            }
            uint32_t bfrag[8][2];
#pragma unroll
            for (int p = 0; p < 4; p++) {
                const uint32_t addr = sw + b_base[p] +
                    (((uint32_t)(ks * 32) + b_lo0) ^ b_key[p]);
                uint32_t r0, r1, r2, r3;
                ldsm_x4(r0, r1, r2, r3, addr);
                bfrag[2 * p][0] = r0; bfrag[2 * p][1] = r1;
                bfrag[2 * p + 1][0] = r2; bfrag[2 * p + 1][1] = r3;
            }
#pragma unroll
            for (int mf = 0; mf < 2; mf++)
#pragma unroll
                for (int nf = 0; nf < 8; nf++)
                    mma16816(acc[mf][nf], afrag[mf], bfrag[nf][0], bfrag[nf][1]);
        }
        if (c < 47) {
            char* sA = smem + ((c + 1) & 1) * 16384;
            char* sB = smem + 32768 + ((c + 1) & 1) * 16384;
#pragma unroll
            for (int i = 0; i < 4; i++) {
                const uint32_t lo = (uint32_t)(hsel * 64 + i * 16) ^ skey;
                *(uint4*)(sA + srow_off + lo) = ra[i];
                *(uint4*)(sB + srow_off + lo) = rb[i];
            }
            __syncthreads();
        }
    }

    // epilogue: bias + split-head scatter C[((b*NH+h)*SEQ+s)*DK + d]
    const int g = lane >> 2;
    const int tc = lane & 3;
    const int h = (n0 + warp_n * 64) >> 6;   // warp n-tile is 64-aligned
#pragma unroll
    for (int mf = 0; mf < 2; mf++) {
#pragma unroll
        for (int nf = 0; nf < 8; nf++) {
            const int row = m0 + warp_m * 32 + mf * 16 + g;
            const int col = n0 + warp_n * 64 + nf * 8 + tc * 2;
            const int d = col & 63;
            const float b0 = bias[col];
            const float b1 = bias[col + 1];
            const int bb0 = row >> 11, s0 = row & (SEQ - 1);
            const int bb1 = (row + 8) >> 11, s1 = (row + 8) & (SEQ - 1);
            float2 v0 = make_float2(acc[mf][nf][0] + b0, acc[mf][nf][1] + b1);
            float2 v1 = make_float2(acc[mf][nf][2] + b0, acc[mf][nf][3] + b1);
            *(float2*)(C + ((size_t)(bb0 * NH + h) * SEQ + s0) * DK + d) = v0;
            *(float2*)(C + ((size_t)(bb1 * NH + h) * SEQ + s1) * DK + d) = v1;
        }
    }
}

// ====================================================================
// Causal flash attention, fp32 SIMT, 8x8 micro-tiles (fma-bound).
// 128 threads, q-tile 128 x k-tile 64. Conflict-free swizzled smem.
// ====================================================================
#define FA_Q_OFF 0          // Qs[d][r]: 64 x 128 floats
#define FA_K_OFF 8192       // Ks[d][c]: 64 rows x 68 floats
#define FA_V_OFF 12544      // Vs[c][d]: 64 rows x 68 floats
#define FA_P_OFF 16896      // Ps[c][r]: 64 rows x 128 floats (xor swizzle)
#define FA_SMEM_FLOATS 25088

__global__ __launch_bounds__(128) void flash_attn(
    const float* __restrict__ Qb, const float* __restrict__ Kb,
    const float* __restrict__ Vb, float* __restrict__ ctx)
{
    extern __shared__ float fsm[];
    float* Qs = fsm + FA_Q_OFF;
    float* Ks = fsm + FA_K_OFF;
    float* Vs = fsm + FA_V_OFF;
    float* Ps = fsm + FA_P_OFF;

    const int tid = threadIdx.x;
    const int bh = blockIdx.y;
    const int qt = (gridDim.x - 1) - blockIdx.x;   // heavy tiles first
    const int q0 = qt * 128;
    const int tx = tid & 7;      // 8 col-groups of 8 -> 64 cols
    const int ty = tid >> 3;     // 16 row-groups of 8 -> 128 rows

    // ---- load Q tile transposed: Qs[d][r], r = tid ----
    {
        const float* src = Qb + ((size_t)bh * SEQ + q0 + tid) * DK;
#pragma unroll
        for (int i4 = 0; i4 < 16; i4++) {
            float4 q = *(const float4*)(src + i4 * 4);
            Qs[(i4 * 4 + 0) * 128 + tid] = q.x;
            Qs[(i4 * 4 + 1) * 128 + tid] = q.y;
            Qs[(i4 * 4 + 2) * 128 + tid] = q.z;
            Qs[(i4 * 4 + 3) * 128 + tid] = q.w;
        }
    }

    float m[8], l[8], o[8][8];
#pragma unroll
    for (int i = 0; i < 8; i++) {
        m[i] = -1e30f;
        l[i] = 0.f;
#pragma unroll
        for (int j = 0; j < 8; j++) o[i][j] = 0.f;
    }

    const int nkt = 2 * qt + 2;
    const int lc = tid >> 1;               // 0..63 : k-col for loading
    const int ldb = (tid & 1) * 32;        // d-base for loading
    const int cg = lc >> 2;
    const int cw = (cg + (cg >> 3)) * 4 + (lc & 3);  // swizzled col word in Ks row

    // K/V vector offsets for compute reads (granule swizzle l + (l>>3))
    const int kv_w0 = tx * 8 + (tx >> 2) * 4;        // first float4 word offset

    for (int kt = 0; kt < nkt; kt++) {
        const int k0 = kt * 64;
        __syncthreads();   // previous iteration's P/V reads complete

        // ---- load K (transposed) and V tiles ----
        {
            const float* kg = Kb + ((size_t)bh * SEQ + k0 + lc) * DK + ldb;
            const float* vg = Vb + ((size_t)bh * SEQ + k0 + lc) * DK + ldb;
#pragma unroll
            for (int i4 = 0; i4 < 8; i4++) {
                float4 kv = *(const float4*)(kg + i4 * 4);
                const int d = ldb + i4 * 4;
                Ks[(d + 0) * 68 + cw] = kv.x;
                Ks[(d + 1) * 68 + cw] = kv.y;
                Ks[(d + 2) * 68 + cw] = kv.z;
                Ks[(d + 3) * 68 + cw] = kv.w;
                float4 vv = *(const float4*)(vg + i4 * 4);
                const int dg = d >> 2;
                *(float4*)(Vs + lc * 68 + (dg + (dg >> 3)) * 4) = vv;
            }
        }
        __syncthreads();

        // ---- S = Q K^T (8x8 per thread) ----
        float s[8][8];
#pragma unroll
        for (int i = 0; i < 8; i++)
#pragma unroll
            for (int j = 0; j < 8; j++) s[i][j] = 0.f;

#pragma unroll 4
        for (int d = 0; d < 64; d++) {
            float4 qa = *(const float4*)(Qs + d * 128 + ty * 8);
            float4 qb = *(const float4*)(Qs + d * 128 + ty * 8 + 4);
            float4 ka = *(const float4*)(Ks + d * 68 + kv_w0);
            float4 kb = *(const float4*)(Ks + d * 68 + kv_w0 + 4);
            const float aa[8] = {qa.x, qa.y, qa.z, qa.w, qb.x, qb.y, qb.z, qb.w};
            const float bb[8] = {ka.x, ka.y, ka.z, ka.w, kb.x, kb.y, kb.z, kb.w};
#pragma unroll
            for (int i = 0; i < 8; i++)
#pragma unroll
                for (int j = 0; j < 8; j++)
                    s[i][j] += aa[i] * bb[j];
        }

        // ---- scale + causal mask (only tiles overlapping diagonal) ----
        const bool diag = (k0 >= q0);
#pragma unroll
        for (int i = 0; i < 8; i++)
#pragma unroll
            for (int j = 0; j < 8; j++) {
                s[i][j] *= 0.125f;
                if (diag && (k0 + tx * 8 + j) > (q0 + ty * 8 + i))
                    s[i][j] = -1e30f;
            }

        // ---- online softmax (row reduce over 8 tx lanes) ----
#pragma unroll
        for (int i = 0; i < 8; i++) {
            float mloc = s[i][0];
#pragma unroll
            for (int j = 1; j < 8; j++) mloc = fmaxf(mloc, s[i][j]);
            mloc = fmaxf(mloc, __shfl_xor_sync(0xffffffffu, mloc, 1));
            mloc = fmaxf(mloc, __shfl_xor_sync(0xffffffffu, mloc, 2));
            mloc = fmaxf(mloc, __shfl_xor_sync(0xffffffffu, mloc, 4));
            const float mnew = fmaxf(m[i], mloc);
            const float alpha = __expf(m[i] - mnew);
            float psum = 0.f;
#pragma unroll
            for (int j = 0; j < 8; j++) {
                const float p = __expf(s[i][j] - mnew);
                s[i][j] = p;
                psum += p;
            }
            psum += __shfl_xor_sync(0xffffffffu, psum, 1);
            psum += __shfl_xor_sync(0xffffffffu, psum, 2);
            psum += __shfl_xor_sync(0xffffffffu, psum, 4);
            l[i] = l[i] * alpha + psum;
            m[i] = mnew;
#pragma unroll
            for (int j = 0; j < 8; j++) o[i][j] *= alpha;
        }

        // ---- store P transposed to Ps[c][r] with xor-in-c swizzle ----
#pragma unroll
        for (int j = 0; j < 8; j++) {
            const int c = tx * 8 + j;
            float* prow = Ps + c * 128;
            const int g0 = (ty * 2) ^ (c & 31);
            const int g1 = (ty * 2 + 1) ^ (c & 31);
            *(float4*)(prow + g0 * 4) = make_float4(s[0][j], s[1][j], s[2][j], s[3][j]);
            *(float4*)(prow + g1 * 4) = make_float4(s[4][j], s[5][j], s[6][j], s[7][j]);
        }
        __syncthreads();

        // ---- O += P @ V ----
#pragma unroll 4
        for (int c = 0; c < 64; c++) {
            const float* prow = Ps + c * 128;
            float4 pa = *(const float4*)(prow + (((ty * 2) ^ (c & 31)) << 2));
            float4 pb = *(const float4*)(prow + (((ty * 2 + 1) ^ (c & 31)) << 2));
            float4 va = *(const float4*)(Vs + c * 68 + kv_w0);
            float4 vb = *(const float4*)(Vs + c * 68 + kv_w0 + 4);
            const float pp[8] = {pa.x, pa.y, pa.z, pa.w, pb.x, pb.y, pb.z, pb.w};
            const float vv[8] = {va.x, va.y, va.z, va.w, vb.x, vb.y, vb.z, vb.w};
#pragma unroll
            for (int i = 0; i < 8; i++)
#pragma unroll
                for (int j = 0; j < 8; j++)
                    o[i][j] += pp[i] * vv[j];
        }
    }

    // ---- normalize + store to ctx[(b*SEQ+s)*D_MODEL + h*DK + d] ----
    const int b = bh >> 4;
    const int h = bh & 15;
#pragma unroll
    for (int i = 0; i < 8; i++) {
        const float inv = 1.0f / l[i];
        const int srow = q0 + ty * 8 + i;
        float* dst = ctx + ((size_t)b * SEQ + srow) * D_MODEL + h * DK + tx * 8;
        *(float4*)(dst + 0) = make_float4(o[i][0] * inv, o[i][1] * inv, o[i][2] * inv, o[i][3] * inv);
        *(float4*)(dst + 4) = make_float4(o[i][4] * inv, o[i][5] * inv, o[i][6] * inv, o[i][7] * inv);
    }
}

// ====================================================================
extern "C" void kernel_launch(void* const* d_in, const int* in_sizes, int n_in,
                              void* d_out, int out_size)
{
    const float* query  = (const float*)d_in[0];
    const float* key_in = (const float*)d_in[1];
    const float* value  = (const float*)d_in[2];
    // d_in[3] = mask (causal tril, known statically -> ignored)
    const float* w_q = (const float*)d_in[4];
    const float* b_q = (const float*)d_in[5];
    const float* w_k = (const float*)d_in[6];
    const float* b_k = (const float*)d_in[7];
    const float* w_v = (const float*)d_in[8];
    const float* b_v = (const float*)d_in[9];
    const float* w_o = (const float*)d_in[10];
    const float* b_o = (const float*)d_in[11];

    float *qp, *kp, *vp, *cp;
    __nv_bfloat16 *a2, *w2;
    cudaGetSymbolAddress((void**)&qp, g_q);
    cudaGetSymbolAddress((void**)&kp, g_k);
    cudaGetSymbolAddress((void**)&vp, g_v);
    cudaGetSymbolAddress((void**)&cp, g_ctx);
    cudaGetSymbolAddress((void**)&a2, g_a2);
    cudaGetSymbolAddress((void**)&w2, g_w2);

    const int GEMM_SMEM = 65536;
    const int FA_SMEM = FA_SMEM_FLOATS * 4;
    cudaFuncSetAttribute(gemm_mma, cudaFuncAttributeMaxDynamicSharedMemorySize, GEMM_SMEM);
    cudaFuncSetAttribute(gemm_mma_split, cudaFuncAttributeMaxDynamicSharedMemorySize, GEMM_SMEM);
    cudaFuncSetAttribute(flash_attn, cudaFuncAttributeMaxDynamicSharedMemorySize, FA_SMEM);

    const dim3 gg(D_MODEL / 128, MTOT / 128);            // (8, 32)
    const int convA_blocks = MTOT * D_MODEL / 4 / 256;   // 4096
    const int convW_blocks = D_MODEL * D_MODEL / 4 / 256;

    conv_split<<<convA_blocks, 256>>>(query, a2);
    conv_split<<<convW_blocks, 256>>>(w_q, w2);
    gemm_mma_split<<<gg, 256, GEMM_SMEM>>>(a2, w2, b_q, qp);

    conv_split<<<convA_blocks, 256>>>(key_in, a2);
    conv_split<<<convW_blocks, 256>>>(w_k, w2);
    gemm_mma_split<<<gg, 256, GEMM_SMEM>>>(a2, w2, b_k, kp);

    conv_split<<<convA_blocks, 256>>>(value, a2);
    conv_split<<<convW_blocks, 256>>>(w_v, w2);
    gemm_mma_split<<<gg, 256, GEMM_SMEM>>>(a2, w2, b_v, vp);

    flash_attn<<<dim3(SEQ / 128, BATCH * NH), 128, FA_SMEM>>>(qp, kp, vp, cp);

    conv_split<<<convA_blocks, 256>>>(cp, a2);
    conv_split<<<convW_blocks, 256>>>(w_o, w2);
    gemm_mma<<<gg, 256, GEMM_SMEM>>>(a2, w2, b_o, (float*)d_out, 0);
}

// round 7
// speedup vs baseline: 2.5525x; 1.6566x over previous
#include <cuda_runtime.h>
#include <cuda_bf16.h>
#include <cstdint>
#include <math.h>

#define D_MODEL 1024
#define NH      16
#define DK      64
#define BATCH   2
#define SEQ     2048
#define MTOT    (BATCH * SEQ)   // 4096

// ---------------- scratch (no allocations allowed) ----------------
__device__ float g_q[BATCH * NH * SEQ * DK];     // [B,H,S,DK]
__device__ float g_k[BATCH * NH * SEQ * DK];
__device__ float g_v[BATCH * NH * SEQ * DK];
__device__ float g_ctx[BATCH * SEQ * D_MODEL];   // [B,S,D_MODEL]
__device__ __nv_bfloat16 g_a2[MTOT * 2 * D_MODEL];     // [M, 2048]: hi | lo
__device__ __nv_bfloat16 g_w2[D_MODEL * 2 * D_MODEL];  // [N, 2048]: hi | lo

// ================= helpers =================
__device__ __forceinline__ uint32_t smem_to_u32(const void* p) {
    uint32_t a;
    asm("{ .reg .u64 t; cvta.to.shared.u64 t, %1; cvt.u32.u64 %0, t; }" : "=r"(a) : "l"(p));
    return a;
}
__device__ __forceinline__ void ldsm_x4(uint32_t& r0, uint32_t& r1, uint32_t& r2, uint32_t& r3,
                                        uint32_t addr) {
    asm volatile("ldmatrix.sync.aligned.m8n8.x4.shared.b16 {%0,%1,%2,%3}, [%4];"
                 : "=r"(r0), "=r"(r1), "=r"(r2), "=r"(r3) : "r"(addr));
}
__device__ __forceinline__ void ldsm_x4_t(uint32_t& r0, uint32_t& r1, uint32_t& r2, uint32_t& r3,
                                          uint32_t addr) {
    asm volatile("ldmatrix.sync.aligned.m8n8.x4.trans.shared.b16 {%0,%1,%2,%3}, [%4];"
                 : "=r"(r0), "=r"(r1), "=r"(r2), "=r"(r3) : "r"(addr));
}
__device__ __forceinline__ void mma16816(float* d, const uint32_t* a, uint32_t b0, uint32_t b1) {
    asm volatile("mma.sync.aligned.m16n8k16.row.col.f32.bf16.bf16.f32 "
                 "{%0,%1,%2,%3}, {%4,%5,%6,%7}, {%8,%9}, {%0,%1,%2,%3};"
                 : "+f"(d[0]), "+f"(d[1]), "+f"(d[2]), "+f"(d[3])
                 : "r"(a[0]), "r"(a[1]), "r"(a[2]), "r"(a[3]), "r"(b0), "r"(b1));
}
__device__ __forceinline__ void split8(float4 x0, float4 x1, uint4& hi, uint4& lo) {
    float v[8] = {x0.x, x0.y, x0.z, x0.w, x1.x, x1.y, x1.z, x1.w};
    __nv_bfloat16 hb[8], lb[8];
#pragma unroll
    for (int i = 0; i < 8; i++) {
        hb[i] = __float2bfloat16(v[i]);
        lb[i] = __float2bfloat16(v[i] - __bfloat162float(hb[i]));
    }
    hi = *(uint4*)hb;
    lo = *(uint4*)lb;
}

// ====================================================================
// Split conversion: fp32 [R,1024] -> bf16 [R,2048] (hi | lo)
// ====================================================================
__global__ __launch_bounds__(256) void conv_split(const float* __restrict__ in,
                                                  __nv_bfloat16* __restrict__ out)
{
    const int idx4 = blockIdx.x * blockDim.x + threadIdx.x;
    const int row = idx4 >> 8;
    const int col = (idx4 & 255) * 4;
    float4 x = *(const float4*)(in + (size_t)row * 1024 + col);
    __nv_bfloat16 h0 = __float2bfloat16(x.x);
    __nv_bfloat16 h1 = __float2bfloat16(x.y);
    __nv_bfloat16 h2 = __float2bfloat16(x.z);
    __nv_bfloat16 h3 = __float2bfloat16(x.w);
    __nv_bfloat16 l0 = __float2bfloat16(x.x - __bfloat162float(h0));
    __nv_bfloat16 l1 = __float2bfloat16(x.y - __bfloat162float(h1));
    __nv_bfloat16 l2 = __float2bfloat16(x.z - __bfloat162float(h2));
    __nv_bfloat16 l3 = __float2bfloat16(x.w - __bfloat162float(h3));
    __nv_bfloat16* oh = out + (size_t)row * 2048 + col;
    __nv_bfloat16* ol = oh + 1024;
    *(__nv_bfloat162*)(oh + 0) = __nv_bfloat162(h0, h1);
    *(__nv_bfloat162*)(oh + 2) = __nv_bfloat162(h2, h3);
    *(__nv_bfloat162*)(ol + 0) = __nv_bfloat162(l0, l1);
    *(__nv_bfloat162*)(ol + 2) = __nv_bfloat162(l2, l3);
}

// ====================================================================
// HMMA GEMM: C = A @ W^T + bias via 3-segment bf16 split (K' = 3072).
// CTA 128x128, 256 threads = 8 warps (4m x 2n), warp tile 32x64.
// ====================================================================
__global__ __launch_bounds__(256) void gemm_mma(
    const __nv_bfloat16* __restrict__ A2, const __nv_bfloat16* __restrict__ W2,
    const float* __restrict__ bias, float* __restrict__ C)
{
    extern __shared__ char smem[];
    const uint32_t sb = smem_to_u32(smem);
    const int tid = threadIdx.x;
    const int lane = tid & 31;
    const int wid = tid >> 5;
    const int warp_m = wid >> 1;
    const int warp_n = wid & 1;
    const int m0 = blockIdx.y * 128;
    const int n0 = blockIdx.x * 128;

    float acc[2][8][4];
#pragma unroll
    for (int mf = 0; mf < 2; mf++)
#pragma unroll
        for (int nf = 0; nf < 8; nf++)
#pragma unroll
            for (int u = 0; u < 4; u++) acc[mf][nf][u] = 0.f;

    const int lrow = tid >> 1;
    const int hsel = tid & 1;
    const __nv_bfloat16* agbase = A2 + (size_t)(m0 + lrow) * 2048 + hsel * 32;
    const __nv_bfloat16* wgbase = W2 + (size_t)(n0 + lrow) * 2048 + hsel * 32;
    const uint32_t skey = (uint32_t)((lrow & 7) << 4);
    const uint32_t srow_off = (uint32_t)(lrow * 128);

    uint32_t a_base[2], a_key[2];
#pragma unroll
    for (int mf = 0; mf < 2; mf++) {
        const int arow = warp_m * 32 + mf * 16 + (lane & 15);
        a_base[mf] = (uint32_t)(arow * 128);
        a_key[mf] = (uint32_t)((arow & 7) << 4);
    }
    const uint32_t a_lo0 = (uint32_t)((lane >> 4) * 16);
    uint32_t b_base[4], b_key[4];
#pragma unroll
    for (int p = 0; p < 4; p++) {
        const int brow = warp_n * 64 + p * 16 + ((lane >> 4) & 1) * 8 + (lane & 7);
        b_base[p] = (uint32_t)(brow * 128);
        b_key[p] = (uint32_t)((brow & 7) << 4);
    }
    const uint32_t b_lo0 = (uint32_t)(((lane >> 3) & 1) * 16);

    uint4 ra[4], rb[4];
    {
#pragma unroll
        for (int i = 0; i < 4; i++) {
            ra[i] = *(const uint4*)(agbase + i * 8);
            rb[i] = *(const uint4*)(wgbase + i * 8);
        }
        char* sA = smem;
        char* sB = smem + 32768;
#pragma unroll
        for (int i = 0; i < 4; i++) {
            const uint32_t lo = (uint32_t)(hsel * 64 + i * 16) ^ skey;
            *(uint4*)(sA + srow_off + lo) = ra[i];
            *(uint4*)(sB + srow_off + lo) = rb[i];
        }
    }
    __syncthreads();

    for (int c = 0; c < 48; c++) {
        if (c < 47) {
            const int cn = c + 1;
            const int seg = cn >> 4;
            const int kc = (cn & 15) << 6;
            const __nv_bfloat16* ap = agbase + kc + (seg == 1 ? 1024 : 0);
            const __nv_bfloat16* wp = wgbase + kc + (seg == 2 ? 1024 : 0);
#pragma unroll
            for (int i = 0; i < 4; i++) {
                ra[i] = *(const uint4*)(ap + i * 8);
                rb[i] = *(const uint4*)(wp + i * 8);
            }
        }
        const int buf = c & 1;
        const uint32_t sa = sb + buf * 16384;
        const uint32_t sw = sb + 32768 + buf * 16384;
#pragma unroll
        for (int ks = 0; ks < 4; ks++) {
            uint32_t afrag[2][4];
#pragma unroll
            for (int mf = 0; mf < 2; mf++) {
                const uint32_t addr = sa + a_base[mf] +
                    (((uint32_t)(ks * 32) + a_lo0) ^ a_key[mf]);
                ldsm_x4(afrag[mf][0], afrag[mf][1], afrag[mf][2], afrag[mf][3], addr);
            }
            uint32_t bfrag[8][2];
#pragma unroll
            for (int p = 0; p < 4; p++) {
                const uint32_t addr = sw + b_base[p] +
                    (((uint32_t)(ks * 32) + b_lo0) ^ b_key[p]);
                uint32_t r0, r1, r2, r3;
                ldsm_x4(r0, r1, r2, r3, addr);
                bfrag[2 * p][0] = r0; bfrag[2 * p][1] = r1;
                bfrag[2 * p + 1][0] = r2; bfrag[2 * p + 1][1] = r3;
            }
#pragma unroll
            for (int mf = 0; mf < 2; mf++)
#pragma unroll
                for (int nf = 0; nf < 8; nf++)
                    mma16816(acc[mf][nf], afrag[mf], bfrag[nf][0], bfrag[nf][1]);
        }
        if (c < 47) {
            char* sA = smem + ((c + 1) & 1) * 16384;
            char* sB = smem + 32768 + ((c + 1) & 1) * 16384;
#pragma unroll
            for (int i = 0; i < 4; i++) {
                const uint32_t lo = (uint32_t)(hsel * 64 + i * 16) ^ skey;
                *(uint4*)(sA + srow_off + lo) = ra[i];
                *(uint4*)(sB + srow_off + lo) = rb[i];
            }
            __syncthreads();
        }
    }

    const int g = lane >> 2;
    const int tc = lane & 3;
#pragma unroll
    for (int mf = 0; mf < 2; mf++) {
#pragma unroll
        for (int nf = 0; nf < 8; nf++) {
            const int row = m0 + warp_m * 32 + mf * 16 + g;
            const int col = n0 + warp_n * 64 + nf * 8 + tc * 2;
            const float b0 = bias[col];
            const float b1 = bias[col + 1];
            float2 v0 = make_float2(acc[mf][nf][0] + b0, acc[mf][nf][1] + b1);
            float2 v1 = make_float2(acc[mf][nf][2] + b0, acc[mf][nf][3] + b1);
            *(float2*)(C + (size_t)row * D_MODEL + col) = v0;
            *(float2*)(C + (size_t)(row + 8) * D_MODEL + col) = v1;
        }
    }
}

__global__ __launch_bounds__(256) void gemm_mma_split(
    const __nv_bfloat16* __restrict__ A2, const __nv_bfloat16* __restrict__ W2,
    const float* __restrict__ bias, float* __restrict__ C)
{
    extern __shared__ char smem[];
    const uint32_t sb = smem_to_u32(smem);
    const int tid = threadIdx.x;
    const int lane = tid & 31;
    const int wid = tid >> 5;
    const int warp_m = wid >> 1;
    const int warp_n = wid & 1;
    const int m0 = blockIdx.y * 128;
    const int n0 = blockIdx.x * 128;

    float acc[2][8][4];
#pragma unroll
    for (int mf = 0; mf < 2; mf++)
#pragma unroll
        for (int nf = 0; nf < 8; nf++)
#pragma unroll
            for (int u = 0; u < 4; u++) acc[mf][nf][u] = 0.f;

    const int lrow = tid >> 1;
    const int hsel = tid & 1;
    const __nv_bfloat16* agbase = A2 + (size_t)(m0 + lrow) * 2048 + hsel * 32;
    const __nv_bfloat16* wgbase = W2 + (size_t)(n0 + lrow) * 2048 + hsel * 32;
    const uint32_t skey = (uint32_t)((lrow & 7) << 4);
    const uint32_t srow_off = (uint32_t)(lrow * 128);

    uint32_t a_base[2], a_key[2];
#pragma unroll
    for (int mf = 0; mf < 2; mf++) {
        const int arow = warp_m * 32 + mf * 16 + (lane & 15);
        a_base[mf] = (uint32_t)(arow * 128);
        a_key[mf] = (uint32_t)((arow & 7) << 4);
    }
    const uint32_t a_lo0 = (uint32_t)((lane >> 4) * 16);
    uint32_t b_base[4], b_key[4];
#pragma unroll
    for (int p = 0; p < 4; p++) {
        const int brow = warp_n * 64 + p * 16 + ((lane >> 4) & 1) * 8 + (lane & 7);
        b_base[p] = (uint32_t)(brow * 128);
        b_key[p] = (uint32_t)((brow & 7) << 4);
    }
    const uint32_t b_lo0 = (uint32_t)(((lane >> 3) & 1) * 16);

    uint4 ra[4], rb[4];
    {
#pragma unroll
        for (int i = 0; i < 4; i++) {
            ra[i] = *(const uint4*)(agbase + i * 8);
            rb[i] = *(const uint4*)(wgbase + i * 8);
        }
        char* sA = smem;
        char* sB = smem + 32768;
#pragma unroll
        for (int i = 0; i < 4; i++) {
            const uint32_t lo = (uint32_t)(hsel * 64 + i * 16) ^ skey;
            *(uint4*)(sA + srow_off + lo) = ra[i];
            *(uint4*)(sB + srow_off + lo) = rb[i];
        }
    }
    __syncthreads();

    for (int c = 0; c < 48; c++) {
        if (c < 47) {
            const int cn = c + 1;
            const int seg = cn >> 4;
            const int kc = (cn & 15) << 6;
            const __nv_bfloat16* ap = agbase + kc + (seg == 1 ? 1024 : 0);
            const __nv_bfloat16* wp = wgbase + kc + (seg == 2 ? 1024 : 0);
#pragma unroll
            for (int i = 0; i < 4; i++) {
                ra[i] = *(const uint4*)(ap + i * 8);
                rb[i] = *(const uint4*)(wp + i * 8);
            }
        }
        const int buf = c & 1;
        const uint32_t sa = sb + buf * 16384;
        const uint32_t sw = sb + 32768 + buf * 16384;
#pragma unroll
        for (int ks = 0; ks < 4; ks++) {
            uint32_t afrag[2][4];
#pragma unroll
            for (int mf = 0; mf < 2; mf++) {
                const uint32_t addr = sa + a_base[mf] +
                    (((uint32_t)(ks * 32) + a_lo0) ^ a_key[mf]);
                ldsm_x4(afrag[mf][0], afrag[mf][1], afrag[mf][2], afrag[mf][3], addr);
            }
            uint32_t bfrag[8][2];
#pragma unroll
            for (int p = 0; p < 4; p++) {
                const uint32_t addr = sw + b_base[p] +
                    (((uint32_t)(ks * 32) + b_lo0) ^ b_key[p]);
                uint32_t r0, r1, r2, r3;
                ldsm_x4(r0, r1, r2, r3, addr);
                bfrag[2 * p][0] = r0; bfrag[2 * p][1] = r1;
                bfrag[2 * p + 1][0] = r2; bfrag[2 * p + 1][1] = r3;
            }
#pragma unroll
            for (int mf = 0; mf < 2; mf++)
#pragma unroll
                for (int nf = 0; nf < 8; nf++)
                    mma16816(acc[mf][nf], afrag[mf], bfrag[nf][0], bfrag[nf][1]);
        }
        if (c < 47) {
            char* sA = smem + ((c + 1) & 1) * 16384;
            char* sB = smem + 32768 + ((c + 1) & 1) * 16384;
#pragma unroll
            for (int i = 0; i < 4; i++) {
                const uint32_t lo = (uint32_t)(hsel * 64 + i * 16) ^ skey;
                *(uint4*)(sA + srow_off + lo) = ra[i];
                *(uint4*)(sB + srow_off + lo) = rb[i];
            }
            __syncthreads();
        }
    }

    const int g = lane >> 2;
    const int tc = lane & 3;
    const int h = (n0 + warp_n * 64) >> 6;
#pragma unroll
    for (int mf = 0; mf < 2; mf++) {
#pragma unroll
        for (int nf = 0; nf < 8; nf++) {
            const int row = m0 + warp_m * 32 + mf * 16 + g;
            const int col = n0 + warp_n * 64 + nf * 8 + tc * 2;
            const int d = col & 63;
            const float b0 = bias[col];
            const float b1 = bias[col + 1];
            const int bb0 = row >> 11, s0 = row & (SEQ - 1);
            const int bb1 = (row + 8) >> 11, s1 = (row + 8) & (SEQ - 1);
            float2 v0 = make_float2(acc[mf][nf][0] + b0, acc[mf][nf][1] + b1);
            float2 v1 = make_float2(acc[mf][nf][2] + b0, acc[mf][nf][3] + b1);
            *(float2*)(C + ((size_t)(bb0 * NH + h) * SEQ + s0) * DK + d) = v0;
            *(float2*)(C + ((size_t)(bb1 * NH + h) * SEQ + s1) * DK + d) = v1;
        }
    }
}

// ====================================================================
// Causal flash attention via HMMA bf16 with hi/lo split precision.
// CTA 256 thr (8 warps), q-tile 128 (16 rows/warp), k-tile 64.
// smem: Qh,Ql[128][64] | Kh,Kl[64][64] | Vh,Vl[64][64] | Ph,Pl[128][64]
// all rows 128B with xor-16B swizzle key = (row&7)<<4.  Total 96KB.
// ====================================================================
#define QH_O 0
#define QL_O 16384
#define KH_O 32768
#define KL_O 40960
#define VH_O 49152
#define VL_O 57344
#define PH_O 65536
#define PL_O 81920
#define FA_SMEM 98304

__global__ __launch_bounds__(256) void flash_hmma(
    const float* __restrict__ Qb, const float* __restrict__ Kb,
    const float* __restrict__ Vb, float* __restrict__ ctx)
{
    extern __shared__ char fsm[];
    const uint32_t sb = smem_to_u32(fsm);
    const int tid = threadIdx.x;
    const int lane = tid & 31;
    const int w = tid >> 5;
    const int bh = blockIdx.y;
    const int qt = (int)(gridDim.x - 1 - blockIdx.x);   // heavy tiles first
    const int q0 = qt * 128;

    // ---- load Q tile, scale by 1/8, split hi/lo into smem ----
    {
        const int row = tid >> 1;
        const int dbase = (tid & 1) * 32;
        const float* src = Qb + ((size_t)bh * SEQ + q0 + row) * DK + dbase;
        const uint32_t ro = (uint32_t)(row * 128);
        const uint32_t key = (uint32_t)((row & 7) << 4);
#pragma unroll
        for (int u = 0; u < 4; u++) {
            float4 x0 = *(const float4*)(src + u * 8);
            float4 x1 = *(const float4*)(src + u * 8 + 4);
            x0.x *= 0.125f; x0.y *= 0.125f; x0.z *= 0.125f; x0.w *= 0.125f;
            x1.x *= 0.125f; x1.y *= 0.125f; x1.z *= 0.125f; x1.w *= 0.125f;
            uint4 hi, lo;
            split8(x0, x1, hi, lo);
            const uint32_t off = ro + (((uint32_t)(dbase * 2 + u * 16)) ^ key);
            *(uint4*)(fsm + QH_O + off) = hi;
            *(uint4*)(fsm + QL_O + off) = lo;
        }
    }

    float mst[2] = {-1e30f, -1e30f};
    float lst[2] = {0.f, 0.f};
    float o[8][4];
#pragma unroll
    for (int nf = 0; nf < 8; nf++)
#pragma unroll
        for (int u = 0; u < 4; u++) o[nf][u] = 0.f;

    const int g = lane >> 2;
    const int tc = lane & 3;
    const int wrow = w * 16;

    // A-operand addressing (Q and P tiles share it: 16 rows per warp)
    const int arow = wrow + (lane & 15);
    const uint32_t a_ro = (uint32_t)(arow * 128);
    const uint32_t a_key = (uint32_t)((arow & 7) << 4);
    const uint32_t a_lo0 = (uint32_t)((lane >> 4) * 16);
    // B non-trans (K [n][k] rows)
    uint32_t kb_ro[4], kb_key[4];
#pragma unroll
    for (int p = 0; p < 4; p++) {
        const int brow = p * 16 + ((lane >> 4) & 1) * 8 + (lane & 7);
        kb_ro[p] = (uint32_t)(brow * 128);
        kb_key[p] = (uint32_t)((brow & 7) << 4);
    }
    const uint32_t b_lo0 = (uint32_t)(((lane >> 3) & 1) * 16);
    // B trans (V [k][n] rows): krow = ks*16 + v_radd, key = (lane&7)<<4
    const uint32_t v_radd = (uint32_t)(((lane >> 3) & 1) * 8 + (lane & 7));
    const uint32_t v_key = (uint32_t)((lane & 7) << 4);
    const uint32_t v_cadd = (uint32_t)(((lane >> 4) & 1) * 16);

    const int nkt = 2 * qt + 2;
    const int wmax = q0 + wrow + 15;

    for (int kt = 0; kt < nkt; kt++) {
        const int k0 = kt * 64;
        __syncthreads();   // previous iteration's smem reads done

        // ---- load K/V tile, split hi/lo ----
        {
            const int row = tid >> 2;
            const int dbase = (tid & 3) * 16;
            const float* ksrc = Kb + ((size_t)bh * SEQ + k0 + row) * DK + dbase;
            const float* vsrc = Vb + ((size_t)bh * SEQ + k0 + row) * DK + dbase;
            const uint32_t ro = (uint32_t)(row * 128);
            const uint32_t key = (uint32_t)((row & 7) << 4);
#pragma unroll
            for (int u = 0; u < 2; u++) {
                const uint32_t off = ro + (((uint32_t)(dbase * 2 + u * 16)) ^ key);
                float4 a0 = *(const float4*)(ksrc + u * 8);
                float4 a1 = *(const float4*)(ksrc + u * 8 + 4);
                uint4 hi, lo;
                split8(a0, a1, hi, lo);
                *(uint4*)(fsm + KH_O + off) = hi;
                *(uint4*)(fsm + KL_O + off) = lo;
                float4 b0 = *(const float4*)(vsrc + u * 8);
                float4 b1 = *(const float4*)(vsrc + u * 8 + 4);
                split8(b0, b1, hi, lo);
                *(uint4*)(fsm + VH_O + off) = hi;
                *(uint4*)(fsm + VL_O + off) = lo;
            }
        }
        __syncthreads();

        if (k0 <= wmax) {
            // ---- S = (scaled Q) K^T, 3 segments ----
            float s[8][4];
#pragma unroll
            for (int nf = 0; nf < 8; nf++)
#pragma unroll
                for (int u = 0; u < 4; u++) s[nf][u] = 0.f;

#pragma unroll
            for (int seg = 0; seg < 3; seg++) {
                const uint32_t Ab = sb + (seg == 1 ? QL_O : QH_O);
                const uint32_t Bb = sb + (seg == 2 ? KL_O : KH_O);
#pragma unroll
                for (int ks = 0; ks < 4; ks++) {
                    uint32_t af[4];
                    ldsm_x4(af[0], af[1], af[2], af[3],
                            Ab + a_ro + (((uint32_t)(ks * 32) + a_lo0) ^ a_key));
#pragma unroll
                    for (int p = 0; p < 4; p++) {
                        uint32_t r0, r1, r2, r3;
                        ldsm_x4(r0, r1, r2, r3,
                                Bb + kb_ro[p] + (((uint32_t)(ks * 32) + b_lo0) ^ kb_key[p]));
                        mma16816(s[2 * p], af, r0, r1);
                        mma16816(s[2 * p + 1], af, r2, r3);
                    }
                }
            }

            // ---- causal mask ----
            const int r_lo = q0 + wrow + g;
            const int r_hi = r_lo + 8;
            if (k0 + 63 > q0 + wrow) {
#pragma unroll
                for (int nf = 0; nf < 8; nf++) {
                    const int c0 = k0 + nf * 8 + tc * 2;
                    if (c0 > r_lo)     s[nf][0] = -1e30f;
                    if (c0 + 1 > r_lo) s[nf][1] = -1e30f;
                    if (c0 > r_hi)     s[nf][2] = -1e30f;
                    if (c0 + 1 > r_hi) s[nf][3] = -1e30f;
                }
            }

            // ---- online softmax (two rows per lane; reduce over 4-lane quad) ----
#pragma unroll
            for (int h2 = 0; h2 < 2; h2++) {
                const int i0 = h2 * 2;
                float mloc = s[0][i0];
#pragma unroll
                for (int nf = 0; nf < 8; nf++) {
                    mloc = fmaxf(mloc, s[nf][i0]);
                    mloc = fmaxf(mloc, s[nf][i0 + 1]);
                }
                mloc = fmaxf(mloc, __shfl_xor_sync(0xffffffffu, mloc, 1));
                mloc = fmaxf(mloc, __shfl_xor_sync(0xffffffffu, mloc, 2));
                const float mnew = fmaxf(mst[h2], mloc);
                const float alpha = __expf(mst[h2] - mnew);
                float psum = 0.f;
#pragma unroll
                for (int nf = 0; nf < 8; nf++) {
                    const float p0 = __expf(s[nf][i0] - mnew);
                    const float p1 = __expf(s[nf][i0 + 1] - mnew);
                    s[nf][i0] = p0; s[nf][i0 + 1] = p1;
                    psum += p0 + p1;
                }
                psum += __shfl_xor_sync(0xffffffffu, psum, 1);
                psum += __shfl_xor_sync(0xffffffffu, psum, 2);
                lst[h2] = lst[h2] * alpha + psum;
                mst[h2] = mnew;
#pragma unroll
                for (int nf = 0; nf < 8; nf++) {
                    o[nf][i0] *= alpha;
                    o[nf][i0 + 1] *= alpha;
                }
            }

            // ---- write P (hi/lo split) to smem ----
            {
                const int prow0 = wrow + g;
                const uint32_t pkey = (uint32_t)((g & 7) << 4);
                const uint32_t ro0 = (uint32_t)(prow0 * 128);
                const uint32_t ro1 = (uint32_t)((prow0 + 8) * 128);
#pragma unroll
                for (int nf = 0; nf < 8; nf++) {
                    const uint32_t cb = (uint32_t)(nf * 16 + tc * 4) ^ pkey;
                    __nv_bfloat16 h0 = __float2bfloat16(s[nf][0]);
                    __nv_bfloat16 h1 = __float2bfloat16(s[nf][1]);
                    __nv_bfloat16 l0 = __float2bfloat16(s[nf][0] - __bfloat162float(h0));
                    __nv_bfloat16 l1 = __float2bfloat16(s[nf][1] - __bfloat162float(h1));
                    *(__nv_bfloat162*)(fsm + PH_O + ro0 + cb) = __nv_bfloat162(h0, h1);
                    *(__nv_bfloat162*)(fsm + PL_O + ro0 + cb) = __nv_bfloat162(l0, l1);
                    __nv_bfloat16 h2b = __float2bfloat16(s[nf][2]);
                    __nv_bfloat16 h3b = __float2bfloat16(s[nf][3]);
                    __nv_bfloat16 l2b = __float2bfloat16(s[nf][2] - __bfloat162float(h2b));
                    __nv_bfloat16 l3b = __float2bfloat16(s[nf][3] - __bfloat162float(h3b));
                    *(__nv_bfloat162*)(fsm + PH_O + ro1 + cb) = __nv_bfloat162(h2b, h3b);
                    *(__nv_bfloat162*)(fsm + PL_O + ro1 + cb) = __nv_bfloat162(l2b, l3b);
                }
            }
            __syncwarp();

            // ---- O += P @ V, 3 segments (V via ldmatrix.trans) ----
#pragma unroll
            for (int seg = 0; seg < 3; seg++) {
                const uint32_t Ab = sb + (seg == 1 ? PL_O : PH_O);
                const uint32_t Bb = sb + (seg == 2 ? VL_O : VH_O);
#pragma unroll
                for (int ks = 0; ks < 4; ks++) {
                    uint32_t af[4];
                    ldsm_x4(af[0], af[1], af[2], af[3],
                            Ab + a_ro + (((uint32_t)(ks * 32) + a_lo0) ^ a_key));
                    const uint32_t kro = (uint32_t)(ks * 16 + v_radd) * 128;
#pragma unroll
                    for (int p = 0; p < 4; p++) {
                        uint32_t r0, r1, r2, r3;
                        ldsm_x4_t(r0, r1, r2, r3,
                                  Bb + kro + (((uint32_t)(p * 32) + v_cadd) ^ v_key));
                        mma16816(o[2 * p], af, r0, r1);
                        mma16816(o[2 * p + 1], af, r2, r3);
                    }
                }
            }
        }
    }

    // ---- normalize + store ctx[(b*SEQ+r)*D_MODEL + h*64 + d] ----
    const int b = bh >> 4;
    const int hh = bh & 15;
    const float inv0 = 1.0f / lst[0];
    const float inv1 = 1.0f / lst[1];
    const int r0 = q0 + wrow + g;
    float* d0 = ctx + ((size_t)b * SEQ + r0) * D_MODEL + hh * DK + tc * 2;
    float* d1 = ctx + ((size_t)b * SEQ + r0 + 8) * D_MODEL + hh * DK + tc * 2;
#pragma unroll
    for (int nf = 0; nf < 8; nf++) {
        *(float2*)(d0 + nf * 8) = make_float2(o[nf][0] * inv0, o[nf][1] * inv0);
        *(float2*)(d1 + nf * 8) = make_float2(o[nf][2] * inv1, o[nf][3] * inv1);
    }
}

// ====================================================================
extern "C" void kernel_launch(void* const* d_in, const int* in_sizes, int n_in,
                              void* d_out, int out_size)
{
    const float* query  = (const float*)d_in[0];
    const float* key_in = (const float*)d_in[1];
    const float* value  = (const float*)d_in[2];
    // d_in[3] = mask (causal tril, known statically -> ignored)
    const float* w_q = (const float*)d_in[4];
    const float* b_q = (const float*)d_in[5];
    const float* w_k = (const float*)d_in[6];
    const float* b_k = (const float*)d_in[7];
    const float* w_v = (const float*)d_in[8];
    const float* b_v = (const float*)d_in[9];
    const float* w_o = (const float*)d_in[10];
    const float* b_o = (const float*)d_in[11];

    float *qp, *kp, *vp, *cp;
    __nv_bfloat16 *a2, *w2;
    cudaGetSymbolAddress((void**)&qp, g_q);
    cudaGetSymbolAddress((void**)&kp, g_k);
    cudaGetSymbolAddress((void**)&vp, g_v);
    cudaGetSymbolAddress((void**)&cp, g_ctx);
    cudaGetSymbolAddress((void**)&a2, g_a2);
    cudaGetSymbolAddress((void**)&w2, g_w2);

    const int GEMM_SMEM = 65536;
    cudaFuncSetAttribute(gemm_mma, cudaFuncAttributeMaxDynamicSharedMemorySize, GEMM_SMEM);
    cudaFuncSetAttribute(gemm_mma_split, cudaFuncAttributeMaxDynamicSharedMemorySize, GEMM_SMEM);
    cudaFuncSetAttribute(flash_hmma, cudaFuncAttributeMaxDynamicSharedMemorySize, FA_SMEM);

    const dim3 gg(D_MODEL / 128, MTOT / 128);            // (8, 32)
    const int convA_blocks = MTOT * D_MODEL / 4 / 256;   // 4096
    const int convW_blocks = D_MODEL * D_MODEL / 4 / 256;

    conv_split<<<convA_blocks, 256>>>(query, a2);
    conv_split<<<convW_blocks, 256>>>(w_q, w2);
    gemm_mma_split<<<gg, 256, GEMM_SMEM>>>(a2, w2, b_q, qp);

    conv_split<<<convA_blocks, 256>>>(key_in, a2);
    conv_split<<<convW_blocks, 256>>>(w_k, w2);
    gemm_mma_split<<<gg, 256, GEMM_SMEM>>>(a2, w2, b_k, kp);

    conv_split<<<convA_blocks, 256>>>(value, a2);
    conv_split<<<convW_blocks, 256>>>(w_v, w2);
    gemm_mma_split<<<gg, 256, GEMM_SMEM>>>(a2, w2, b_v, vp);

    flash_hmma<<<dim3(SEQ / 128, BATCH * NH), 256, FA_SMEM>>>(qp, kp, vp, cp);

    conv_split<<<convA_blocks, 256>>>(cp, a2);
    conv_split<<<convW_blocks, 256>>>(w_o, w2);
    gemm_mma<<<gg, 256, GEMM_SMEM>>>(a2, w2, b_o, (float*)d_out);
}

// round 8
// speedup vs baseline: 3.0640x; 1.2004x over previous
#include <cuda_runtime.h>
#include <cuda_bf16.h>
#include <cstdint>
#include <math.h>

#define D_MODEL 1024
#define NH      16
#define DK      64
#define BATCH   2
#define SEQ     2048
#define MTOT    (BATCH * SEQ)   // 4096

// ---------------- scratch (no allocations allowed) ----------------
__device__ float g_q[BATCH * NH * SEQ * DK];     // [B,H,S,DK]
__device__ float g_k[BATCH * NH * SEQ * DK];
__device__ float g_v[BATCH * NH * SEQ * DK];
__device__ float g_ctx[BATCH * SEQ * D_MODEL];   // [B,S,D_MODEL]
__device__ __nv_bfloat16 g_a2[3 * MTOT * 2 * D_MODEL];     // 3 x [M,2048] hi|lo
__device__ __nv_bfloat16 g_w2[4 * D_MODEL * 2 * D_MODEL];  // 4 x [N,2048] hi|lo (q,k,v,o)

// ================= helpers =================
__device__ __forceinline__ uint32_t smem_to_u32(const void* p) {
    uint32_t a;
    asm("{ .reg .u64 t; cvta.to.shared.u64 t, %1; cvt.u32.u64 %0, t; }" : "=r"(a) : "l"(p));
    return a;
}
__device__ __forceinline__ void ldsm_x4(uint32_t& r0, uint32_t& r1, uint32_t& r2, uint32_t& r3,
                                        uint32_t addr) {
    asm volatile("ldmatrix.sync.aligned.m8n8.x4.shared.b16 {%0,%1,%2,%3}, [%4];"
                 : "=r"(r0), "=r"(r1), "=r"(r2), "=r"(r3) : "r"(addr));
}
__device__ __forceinline__ void ldsm_x4_t(uint32_t& r0, uint32_t& r1, uint32_t& r2, uint32_t& r3,
                                          uint32_t addr) {
    asm volatile("ldmatrix.sync.aligned.m8n8.x4.trans.shared.b16 {%0,%1,%2,%3}, [%4];"
                 : "=r"(r0), "=r"(r1), "=r"(r2), "=r"(r3) : "r"(addr));
}
__device__ __forceinline__ void mma16816(float* d, const uint32_t* a, uint32_t b0, uint32_t b1) {
    asm volatile("mma.sync.aligned.m16n8k16.row.col.f32.bf16.bf16.f32 "
                 "{%0,%1,%2,%3}, {%4,%5,%6,%7}, {%8,%9}, {%0,%1,%2,%3};"
                 : "+f"(d[0]), "+f"(d[1]), "+f"(d[2]), "+f"(d[3])
                 : "r"(a[0]), "r"(a[1]), "r"(a[2]), "r"(a[3]), "r"(b0), "r"(b1));
}
__device__ __forceinline__ void split8(float4 x0, float4 x1, uint4& hi, uint4& lo) {
    float v[8] = {x0.x, x0.y, x0.z, x0.w, x1.x, x1.y, x1.z, x1.w};
    __nv_bfloat16 hb[8], lb[8];
#pragma unroll
    for (int i = 0; i < 8; i++) {
        hb[i] = __float2bfloat16(v[i]);
        lb[i] = __float2bfloat16(v[i] - __bfloat162float(hb[i]));
    }
    hi = *(uint4*)hb;
    lo = *(uint4*)lb;
}
#define CPA16(dst, src) \
    asm volatile("cp.async.cg.shared.global [%0], [%1], 16;" :: "r"(dst), "l"(src))
#define CPA_COMMIT() asm volatile("cp.async.commit_group;" ::: "memory")
#define CPA_WAIT1()  asm volatile("cp.async.wait_group 1;" ::: "memory")
#define CPA_WAIT0()  asm volatile("cp.async.wait_group 0;" ::: "memory")

// ====================================================================
// Multi-tensor split conversion: up to 4 fp32 [rows,1024] -> bf16 [rows,2048]
// grid: (rows, ntensors); one block per row.
// ====================================================================
__global__ __launch_bounds__(256) void conv_split_n(
    const float* __restrict__ s0, const float* __restrict__ s1,
    const float* __restrict__ s2, const float* __restrict__ s3,
    __nv_bfloat16* __restrict__ out, int rows_each)
{
    const float* srcs[4] = {s0, s1, s2, s3};
    const float* src = srcs[blockIdx.y];
    __nv_bfloat16* dst = out + (size_t)blockIdx.y * rows_each * 2048;
    const int row = blockIdx.x;
    const int col = threadIdx.x * 4;
    float4 x = *(const float4*)(src + (size_t)row * 1024 + col);
    __nv_bfloat16 h0 = __float2bfloat16(x.x);
    __nv_bfloat16 h1 = __float2bfloat16(x.y);
    __nv_bfloat16 h2 = __float2bfloat16(x.z);
    __nv_bfloat16 h3 = __float2bfloat16(x.w);
    __nv_bfloat16 l0 = __float2bfloat16(x.x - __bfloat162float(h0));
    __nv_bfloat16 l1 = __float2bfloat16(x.y - __bfloat162float(h1));
    __nv_bfloat16 l2 = __float2bfloat16(x.z - __bfloat162float(h2));
    __nv_bfloat16 l3 = __float2bfloat16(x.w - __bfloat162float(h3));
    __nv_bfloat16* oh = dst + (size_t)row * 2048 + col;
    __nv_bfloat16* ol = oh + 1024;
    *(__nv_bfloat162*)(oh + 0) = __nv_bfloat162(h0, h1);
    *(__nv_bfloat162*)(oh + 2) = __nv_bfloat162(h2, h3);
    *(__nv_bfloat162*)(ol + 0) = __nv_bfloat162(l0, l1);
    *(__nv_bfloat162*)(ol + 2) = __nv_bfloat162(l2, l3);
}

// ====================================================================
// HMMA GEMM mainloop via cp.async double buffering (no register prefetch).
// CTA 128x128, 256 threads = 8 warps (4m x 2n), K' = 3072, 48 chunks of 64.
// ====================================================================
#define GEMM_PREAMBLE()                                                              \
    const uint32_t sb = smem_to_u32(smem);                                           \
    const int tid = threadIdx.x;                                                     \
    const int lane = tid & 31;                                                       \
    const int wid = tid >> 5;                                                        \
    const int warp_m = wid >> 1;                                                     \
    const int warp_n = wid & 1;                                                      \
    float acc[2][8][4];                                                              \
    _Pragma("unroll")                                                                \
    for (int mf = 0; mf < 2; mf++)                                                   \
        _Pragma("unroll")                                                            \
        for (int nf = 0; nf < 8; nf++)                                               \
            _Pragma("unroll")                                                        \
            for (int u = 0; u < 4; u++) acc[mf][nf][u] = 0.f;                        \
    const int lrow = tid >> 1;                                                       \
    const int hsel = tid & 1;                                                        \
    const __nv_bfloat16* agbase = A2 + (size_t)(m0 + lrow) * 2048 + hsel * 32;       \
    const __nv_bfloat16* wgbase = W2 + (size_t)(n0 + lrow) * 2048 + hsel * 32;       \
    const uint32_t skey = (uint32_t)((lrow & 7) << 4);                               \
    const uint32_t srow_off = (uint32_t)(lrow * 128);                                \
    uint32_t a_base[2], a_key[2];                                                    \
    _Pragma("unroll")                                                                \
    for (int mf = 0; mf < 2; mf++) {                                                 \
        const int arow = warp_m * 32 + mf * 16 + (lane & 15);                        \
        a_base[mf] = (uint32_t)(arow * 128);                                         \
        a_key[mf] = (uint32_t)((arow & 7) << 4);                                     \
    }                                                                                \
    const uint32_t a_lo0 = (uint32_t)((lane >> 4) * 16);                             \
    uint32_t b_base[4], b_key[4];                                                    \
    _Pragma("unroll")                                                                \
    for (int p = 0; p < 4; p++) {                                                    \
        const int brow = warp_n * 64 + p * 16 + ((lane >> 4) & 1) * 8 + (lane & 7);  \
        b_base[p] = (uint32_t)(brow * 128);                                          \
        b_key[p] = (uint32_t)((brow & 7) << 4);                                      \
    }                                                                                \
    const uint32_t b_lo0 = (uint32_t)(((lane >> 3) & 1) * 16);

#define GEMM_LOAD_CHUNK(c, buf) do {                                                 \
    const int seg_ = (c) >> 4;                                                       \
    const int kc_ = ((c) & 15) << 6;                                                 \
    const __nv_bfloat16* ap_ = agbase + kc_ + (seg_ == 1 ? 1024 : 0);                \
    const __nv_bfloat16* wp_ = wgbase + kc_ + (seg_ == 2 ? 1024 : 0);                \
    const uint32_t sA_ = sb + (buf) * 16384;                                         \
    const uint32_t sB_ = sb + 32768 + (buf) * 16384;                                 \
    _Pragma("unroll")                                                                \
    for (int i = 0; i < 4; i++) {                                                    \
        const uint32_t lo_ = (uint32_t)(hsel * 64 + i * 16) ^ skey;                  \
        CPA16(sA_ + srow_off + lo_, ap_ + i * 8);                                    \
        CPA16(sB_ + srow_off + lo_, wp_ + i * 8);                                    \
    }                                                                                \
    CPA_COMMIT();                                                                    \
} while (0)

#define GEMM_MAINLOOP()                                                              \
    GEMM_LOAD_CHUNK(0, 0);                                                           \
    for (int c = 0; c < 48; c++) {                                                   \
        if (c < 47) { GEMM_LOAD_CHUNK(c + 1, (c + 1) & 1); CPA_WAIT1(); }            \
        else        { CPA_WAIT0(); }                                                 \
        __syncthreads();                                                             \
        const uint32_t sa = sb + (c & 1) * 16384;                                    \
        const uint32_t sw = sb + 32768 + (c & 1) * 16384;                            \
        _Pragma("unroll")                                                            \
        for (int ks = 0; ks < 4; ks++) {                                             \
            uint32_t afrag[2][4];                                                    \
            _Pragma("unroll")                                                        \
            for (int mf = 0; mf < 2; mf++) {                                         \
                const uint32_t addr = sa + a_base[mf] +                              \
                    (((uint32_t)(ks * 32) + a_lo0) ^ a_key[mf]);                     \
                ldsm_x4(afrag[mf][0], afrag[mf][1], afrag[mf][2], afrag[mf][3], addr); \
            }                                                                        \
            uint32_t bfrag[8][2];                                                    \
            _Pragma("unroll")                                                        \
            for (int p = 0; p < 4; p++) {                                            \
                const uint32_t addr = sw + b_base[p] +                               \
                    (((uint32_t)(ks * 32) + b_lo0) ^ b_key[p]);                      \
                uint32_t r0, r1, r2, r3;                                             \
                ldsm_x4(r0, r1, r2, r3, addr);                                       \
                bfrag[2 * p][0] = r0; bfrag[2 * p][1] = r1;                          \
                bfrag[2 * p + 1][0] = r2; bfrag[2 * p + 1][1] = r3;                  \
            }                                                                        \
            _Pragma("unroll")                                                        \
            for (int mf = 0; mf < 2; mf++)                                           \
                _Pragma("unroll")                                                    \
                for (int nf = 0; nf < 8; nf++)                                       \
                    mma16816(acc[mf][nf], afrag[mf], bfrag[nf][0], bfrag[nf][1]);    \
        }                                                                            \
        __syncthreads();                                                             \
    }

// QKV projections in one launch: blockIdx.z selects tensor; split-head epilogue.
__global__ __launch_bounds__(256, 2) void gemm_qkv(
    const __nv_bfloat16* __restrict__ a2base, const __nv_bfloat16* __restrict__ w2base,
    const float* __restrict__ bq, const float* __restrict__ bk, const float* __restrict__ bv,
    float* __restrict__ qp, float* __restrict__ kp, float* __restrict__ vp)
{
    extern __shared__ char smem[];
    const int z = blockIdx.z;
    const __nv_bfloat16* A2 = a2base + (size_t)z * MTOT * 2048;
    const __nv_bfloat16* W2 = w2base + (size_t)z * D_MODEL * 2048;
    const float* bias = (z == 0) ? bq : (z == 1) ? bk : bv;
    float* C = (z == 0) ? qp : (z == 1) ? kp : vp;
    const int m0 = blockIdx.y * 128;
    const int n0 = blockIdx.x * 128;

    GEMM_PREAMBLE()
    GEMM_MAINLOOP()

    const int g = lane >> 2;
    const int tc = lane & 3;
    const int h = (n0 + warp_n * 64) >> 6;
#pragma unroll
    for (int mf = 0; mf < 2; mf++) {
#pragma unroll
        for (int nf = 0; nf < 8; nf++) {
            const int row = m0 + warp_m * 32 + mf * 16 + g;
            const int col = n0 + warp_n * 64 + nf * 8 + tc * 2;
            const int d = col & 63;
            const float b0 = bias[col];
            const float b1 = bias[col + 1];
            const int bb0 = row >> 11, s0 = row & (SEQ - 1);
            const int bb1 = (row + 8) >> 11, s1 = (row + 8) & (SEQ - 1);
            float2 v0 = make_float2(acc[mf][nf][0] + b0, acc[mf][nf][1] + b1);
            float2 v1 = make_float2(acc[mf][nf][2] + b0, acc[mf][nf][3] + b1);
            *(float2*)(C + ((size_t)(bb0 * NH + h) * SEQ + s0) * DK + d) = v0;
            *(float2*)(C + ((size_t)(bb1 * NH + h) * SEQ + s1) * DK + d) = v1;
        }
    }
}

// Output projection: row-major epilogue.
__global__ __launch_bounds__(256, 2) void gemm_out(
    const __nv_bfloat16* __restrict__ A2, const __nv_bfloat16* __restrict__ W2,
    const float* __restrict__ bias, float* __restrict__ C)
{
    extern __shared__ char smem[];
    const int m0 = blockIdx.y * 128;
    const int n0 = blockIdx.x * 128;

    GEMM_PREAMBLE()
    GEMM_MAINLOOP()

    const int g = lane >> 2;
    const int tc = lane & 3;
#pragma unroll
    for (int mf = 0; mf < 2; mf++) {
#pragma unroll
        for (int nf = 0; nf < 8; nf++) {
            const int row = m0 + warp_m * 32 + mf * 16 + g;
            const int col = n0 + warp_n * 64 + nf * 8 + tc * 2;
            const float b0 = bias[col];
            const float b1 = bias[col + 1];
            float2 v0 = make_float2(acc[mf][nf][0] + b0, acc[mf][nf][1] + b1);
            float2 v1 = make_float2(acc[mf][nf][2] + b0, acc[mf][nf][3] + b1);
            *(float2*)(C + (size_t)row * D_MODEL + col) = v0;
            *(float2*)(C + (size_t)(row + 8) * D_MODEL + col) = v1;
        }
    }
}

// ====================================================================
// Causal flash attention via HMMA bf16 hi/lo split.
// CTA 256 thr (8 warps); processes TWO q-tiles: qt = blockIdx.x and
// 15 - blockIdx.x  ->  exactly 34 k-tile iterations per CTA (uniform).
// smem 96KB; 2 CTAs/SM.
// ====================================================================
#define QH_O 0
#define QL_O 16384
#define KH_O 32768
#define KL_O 40960
#define VH_O 49152
#define VL_O 57344
#define PH_O 65536
#define PL_O 81920
#define FA_SMEM 98304

__global__ __launch_bounds__(256, 2) void flash_hmma(
    const float* __restrict__ Qb, const float* __restrict__ Kb,
    const float* __restrict__ Vb, float* __restrict__ ctx)
{
    extern __shared__ char fsm[];
    const uint32_t sb = smem_to_u32(fsm);
    const int tid = threadIdx.x;
    const int lane = tid & 31;
    const int w = tid >> 5;
    const int bh = blockIdx.y;

    const int g = lane >> 2;
    const int tc = lane & 3;
    const int wrow = w * 16;

    const int arow = wrow + (lane & 15);
    const uint32_t a_ro = (uint32_t)(arow * 128);
    const uint32_t a_key = (uint32_t)((arow & 7) << 4);
    const uint32_t a_lo0 = (uint32_t)((lane >> 4) * 16);
    uint32_t kb_ro[4], kb_key[4];
#pragma unroll
    for (int p = 0; p < 4; p++) {
        const int brow = p * 16 + ((lane >> 4) & 1) * 8 + (lane & 7);
        kb_ro[p] = (uint32_t)(brow * 128);
        kb_key[p] = (uint32_t)((brow & 7) << 4);
    }
    const uint32_t b_lo0 = (uint32_t)(((lane >> 3) & 1) * 16);
    const uint32_t v_radd = (uint32_t)(((lane >> 3) & 1) * 8 + (lane & 7));
    const uint32_t v_key = (uint32_t)((lane & 7) << 4);
    const uint32_t v_cadd = (uint32_t)(((lane >> 4) & 1) * 16);

    for (int half = 0; half < 2; half++) {
        const int qt = (half == 0) ? (int)blockIdx.x : 15 - (int)blockIdx.x;
        const int q0 = qt * 128;
        __syncthreads();   // previous half's smem reads complete

        // ---- load Q tile, scale by 1/8, split hi/lo into smem ----
        {
            const int row = tid >> 1;
            const int dbase = (tid & 1) * 32;
            const float* src = Qb + ((size_t)bh * SEQ + q0 + row) * DK + dbase;
            const uint32_t ro = (uint32_t)(row * 128);
            const uint32_t key = (uint32_t)((row & 7) << 4);
#pragma unroll
            for (int u = 0; u < 4; u++) {
                float4 x0 = *(const float4*)(src + u * 8);
                float4 x1 = *(const float4*)(src + u * 8 + 4);
                x0.x *= 0.125f; x0.y *= 0.125f; x0.z *= 0.125f; x0.w *= 0.125f;
                x1.x *= 0.125f; x1.y *= 0.125f; x1.z *= 0.125f; x1.w *= 0.125f;
                uint4 hi, lo;
                split8(x0, x1, hi, lo);
                const uint32_t off = ro + (((uint32_t)(dbase * 2 + u * 16)) ^ key);
                *(uint4*)(fsm + QH_O + off) = hi;
                *(uint4*)(fsm + QL_O + off) = lo;
            }
        }

        float mst[2] = {-1e30f, -1e30f};
        float lst[2] = {0.f, 0.f};
        float o[8][4];
#pragma unroll
        for (int nf = 0; nf < 8; nf++)
#pragma unroll
            for (int u = 0; u < 4; u++) o[nf][u] = 0.f;

        const int nkt = 2 * qt + 2;
        const int wmax = q0 + wrow + 15;

        for (int kt = 0; kt < nkt; kt++) {
            const int k0 = kt * 64;
            __syncthreads();

            // ---- load K/V tile, split hi/lo ----
            {
                const int row = tid >> 2;
                const int dbase = (tid & 3) * 16;
                const float* ksrc = Kb + ((size_t)bh * SEQ + k0 + row) * DK + dbase;
                const float* vsrc = Vb + ((size_t)bh * SEQ + k0 + row) * DK + dbase;
                const uint32_t ro = (uint32_t)(row * 128);
                const uint32_t key = (uint32_t)((row & 7) << 4);
#pragma unroll
                for (int u = 0; u < 2; u++) {
                    const uint32_t off = ro + (((uint32_t)(dbase * 2 + u * 16)) ^ key);
                    float4 a0 = *(const float4*)(ksrc + u * 8);
                    float4 a1 = *(const float4*)(ksrc + u * 8 + 4);
                    uint4 hi, lo;
                    split8(a0, a1, hi, lo);
                    *(uint4*)(fsm + KH_O + off) = hi;
                    *(uint4*)(fsm + KL_O + off) = lo;
                    float4 b0 = *(const float4*)(vsrc + u * 8);
                    float4 b1 = *(const float4*)(vsrc + u * 8 + 4);
                    split8(b0, b1, hi, lo);
                    *(uint4*)(fsm + VH_O + off) = hi;
                    *(uint4*)(fsm + VL_O + off) = lo;
                }
            }
            __syncthreads();

            if (k0 <= wmax) {
                // ---- S = (scaled Q) K^T, 3 segments ----
                float s[8][4];
#pragma unroll
                for (int nf = 0; nf < 8; nf++)
#pragma unroll
                    for (int u = 0; u < 4; u++) s[nf][u] = 0.f;

#pragma unroll
                for (int seg = 0; seg < 3; seg++) {
                    const uint32_t Ab = sb + (seg == 1 ? QL_O : QH_O);
                    const uint32_t Bb = sb + (seg == 2 ? KL_O : KH_O);
#pragma unroll
                    for (int ks = 0; ks < 4; ks++) {
                        uint32_t af[4];
                        ldsm_x4(af[0], af[1], af[2], af[3],
                                Ab + a_ro + (((uint32_t)(ks * 32) + a_lo0) ^ a_key));
#pragma unroll
                        for (int p = 0; p < 4; p++) {
                            uint32_t r0, r1, r2, r3;
                            ldsm_x4(r0, r1, r2, r3,
                                    Bb + kb_ro[p] + (((uint32_t)(ks * 32) + b_lo0) ^ kb_key[p]));
                            mma16816(s[2 * p], af, r0, r1);
                            mma16816(s[2 * p + 1], af, r2, r3);
                        }
                    }
                }

                // ---- causal mask ----
                const int r_lo = q0 + wrow + g;
                const int r_hi = r_lo + 8;
                if (k0 + 63 > q0 + wrow) {
#pragma unroll
                    for (int nf = 0; nf < 8; nf++) {
                        const int c0 = k0 + nf * 8 + tc * 2;
                        if (c0 > r_lo)     s[nf][0] = -1e30f;
                        if (c0 + 1 > r_lo) s[nf][1] = -1e30f;
                        if (c0 > r_hi)     s[nf][2] = -1e30f;
                        if (c0 + 1 > r_hi) s[nf][3] = -1e30f;
                    }
                }

                // ---- online softmax ----
#pragma unroll
                for (int h2 = 0; h2 < 2; h2++) {
                    const int i0 = h2 * 2;
                    float mloc = s[0][i0];
#pragma unroll
                    for (int nf = 0; nf < 8; nf++) {
                        mloc = fmaxf(mloc, s[nf][i0]);
                        mloc = fmaxf(mloc, s[nf][i0 + 1]);
                    }
                    mloc = fmaxf(mloc, __shfl_xor_sync(0xffffffffu, mloc, 1));
                    mloc = fmaxf(mloc, __shfl_xor_sync(0xffffffffu, mloc, 2));
                    const float mnew = fmaxf(mst[h2], mloc);
                    const float alpha = __expf(mst[h2] - mnew);
                    float psum = 0.f;
#pragma unroll
                    for (int nf = 0; nf < 8; nf++) {
                        const float p0 = __expf(s[nf][i0] - mnew);
                        const float p1 = __expf(s[nf][i0 + 1] - mnew);
                        s[nf][i0] = p0; s[nf][i0 + 1] = p1;
                        psum += p0 + p1;
                    }
                    psum += __shfl_xor_sync(0xffffffffu, psum, 1);
                    psum += __shfl_xor_sync(0xffffffffu, psum, 2);
                    lst[h2] = lst[h2] * alpha + psum;
                    mst[h2] = mnew;
#pragma unroll
                    for (int nf = 0; nf < 8; nf++) {
                        o[nf][i0] *= alpha;
                        o[nf][i0 + 1] *= alpha;
                    }
                }

                // ---- write P (hi/lo split) to smem ----
                {
                    const int prow0 = wrow + g;
                    const uint32_t pkey = (uint32_t)((g & 7) << 4);
                    const uint32_t ro0 = (uint32_t)(prow0 * 128);
                    const uint32_t ro1 = (uint32_t)((prow0 + 8) * 128);
#pragma unroll
                    for (int nf = 0; nf < 8; nf++) {
                        const uint32_t cb = (uint32_t)(nf * 16 + tc * 4) ^ pkey;
                        __nv_bfloat16 h0 = __float2bfloat16(s[nf][0]);
                        __nv_bfloat16 h1 = __float2bfloat16(s[nf][1]);
                        __nv_bfloat16 l0 = __float2bfloat16(s[nf][0] - __bfloat162float(h0));
                        __nv_bfloat16 l1 = __float2bfloat16(s[nf][1] - __bfloat162float(h1));
                        *(__nv_bfloat162*)(fsm + PH_O + ro0 + cb) = __nv_bfloat162(h0, h1);
                        *(__nv_bfloat162*)(fsm + PL_O + ro0 + cb) = __nv_bfloat162(l0, l1);
                        __nv_bfloat16 h2b = __float2bfloat16(s[nf][2]);
                        __nv_bfloat16 h3b = __float2bfloat16(s[nf][3]);
                        __nv_bfloat16 l2b = __float2bfloat16(s[nf][2] - __bfloat162float(h2b));
                        __nv_bfloat16 l3b = __float2bfloat16(s[nf][3] - __bfloat162float(h3b));
                        *(__nv_bfloat162*)(fsm + PH_O + ro1 + cb) = __nv_bfloat162(h2b, h3b);
                        *(__nv_bfloat162*)(fsm + PL_O + ro1 + cb) = __nv_bfloat162(l2b, l3b);
                    }
                }
                __syncwarp();

                // ---- O += P @ V, 3 segments (V via ldmatrix.trans) ----
#pragma unroll
                for (int seg = 0; seg < 3; seg++) {
                    const uint32_t Ab = sb + (seg == 1 ? PL_O : PH_O);
                    const uint32_t Bb = sb + (seg == 2 ? VL_O : VH_O);
#pragma unroll
                    for (int ks = 0; ks < 4; ks++) {
                        uint32_t af[4];
                        ldsm_x4(af[0], af[1], af[2], af[3],
                                Ab + a_ro + (((uint32_t)(ks * 32) + a_lo0) ^ a_key));
                        const uint32_t kro = (uint32_t)(ks * 16 + v_radd) * 128;
#pragma unroll
                        for (int p = 0; p < 4; p++) {
                            uint32_t r0, r1, r2, r3;
                            ldsm_x4_t(r0, r1, r2, r3,
                                      Bb + kro + (((uint32_t)(p * 32) + v_cadd) ^ v_key));
                            mma16816(o[2 * p], af, r0, r1);
                            mma16816(o[2 * p + 1], af, r2, r3);
                        }
                    }
                }
            }
        }

        // ---- normalize + store ctx ----
        const int b = bh >> 4;
        const int hh = bh & 15;
        const float inv0 = 1.0f / lst[0];
        const float inv1 = 1.0f / lst[1];
        const int r0 = q0 + wrow + g;
        float* d0 = ctx + ((size_t)b * SEQ + r0) * D_MODEL + hh * DK + tc * 2;
        float* d1 = ctx + ((size_t)b * SEQ + r0 + 8) * D_MODEL + hh * DK + tc * 2;
#pragma unroll
        for (int nf = 0; nf < 8; nf++) {
            *(float2*)(d0 + nf * 8) = make_float2(o[nf][0] * inv0, o[nf][1] * inv0);
            *(float2*)(d1 + nf * 8) = make_float2(o[nf][2] * inv1, o[nf][3] * inv1);
        }
    }
}

// ====================================================================
extern "C" void kernel_launch(void* const* d_in, const int* in_sizes, int n_in,
                              void* d_out, int out_size)
{
    const float* query  = (const float*)d_in[0];
    const float* key_in = (const float*)d_in[1];
    const float* value  = (const float*)d_in[2];
    // d_in[3] = mask (causal tril, known statically -> ignored)
    const float* w_q = (const float*)d_in[4];
    const float* b_q = (const float*)d_in[5];
    const float* w_k = (const float*)d_in[6];
    const float* b_k = (const float*)d_in[7];
    const float* w_v = (const float*)d_in[8];
    const float* b_v = (const float*)d_in[9];
    const float* w_o = (const float*)d_in[10];
    const float* b_o = (const float*)d_in[11];

    float *qp, *kp, *vp, *cp;
    __nv_bfloat16 *a2, *w2;
    cudaGetSymbolAddress((void**)&qp, g_q);
    cudaGetSymbolAddress((void**)&kp, g_k);
    cudaGetSymbolAddress((void**)&vp, g_v);
    cudaGetSymbolAddress((void**)&cp, g_ctx);
    cudaGetSymbolAddress((void**)&a2, g_a2);
    cudaGetSymbolAddress((void**)&w2, g_w2);

    const int GEMM_SMEM = 65536;
    cudaFuncSetAttribute(gemm_qkv, cudaFuncAttributeMaxDynamicSharedMemorySize, GEMM_SMEM);
    cudaFuncSetAttribute(gemm_out, cudaFuncAttributeMaxDynamicSharedMemorySize, GEMM_SMEM);
    cudaFuncSetAttribute(flash_hmma, cudaFuncAttributeMaxDynamicSharedMemorySize, FA_SMEM);

    // 1) convert all 4 weight matrices (hi|lo), one launch
    conv_split_n<<<dim3(1024, 4), 256>>>(w_q, w_k, w_v, w_o, w2, 1024);
    // 2) convert the 3 input tensors, one launch
    conv_split_n<<<dim3(4096, 3), 256>>>(query, key_in, value, nullptr, a2, 4096);
    // 3) Q/K/V projections, one launch (grid z)
    gemm_qkv<<<dim3(8, 32, 3), 256, GEMM_SMEM>>>(a2, w2, b_q, b_k, b_v, qp, kp, vp);
    // 4) attention
    flash_hmma<<<dim3(8, BATCH * NH), 256, FA_SMEM>>>(qp, kp, vp, cp);
    // 5) convert ctx into a2 slot 0
    conv_split_n<<<dim3(4096, 1), 256>>>(cp, nullptr, nullptr, nullptr, a2, 4096);
    // 6) output projection
    gemm_out<<<dim3(8, 32), 256, GEMM_SMEM>>>(a2, w2 + (size_t)3 * D_MODEL * 2048, b_o, (float*)d_out);
}

// round 9
// speedup vs baseline: 3.4138x; 1.1142x over previous
#include <cuda_runtime.h>
#include <cuda_bf16.h>
#include <cstdint>
#include <math.h>

#define D_MODEL 1024
#define NH      16
#define DK      64
#define BATCH   2
#define SEQ     2048
#define MTOT    (BATCH * SEQ)            // 4096
#define NTOK    (BATCH * NH * SEQ * DK)  // 4194304

// ---------------- scratch (no allocations allowed) ----------------
__device__ __nv_bfloat16 g_a2[3 * MTOT * 2 * D_MODEL];     // 3 x [M,2048] hi|lo
__device__ __nv_bfloat16 g_w2[4 * D_MODEL * 2 * D_MODEL];  // 4 x [N,2048] hi|lo (q,k,v,o)
__device__ __nv_bfloat16 g_q2[2 * NTOK];   // [B,H,S,DK] hi plane | lo plane (Q pre-scaled 1/8)
__device__ __nv_bfloat16 g_k2[2 * NTOK];
__device__ __nv_bfloat16 g_v2[2 * NTOK];

// ================= helpers =================
__device__ __forceinline__ uint32_t smem_to_u32(const void* p) {
    uint32_t a;
    asm("{ .reg .u64 t; cvta.to.shared.u64 t, %1; cvt.u32.u64 %0, t; }" : "=r"(a) : "l"(p));
    return a;
}
__device__ __forceinline__ void ldsm_x4(uint32_t& r0, uint32_t& r1, uint32_t& r2, uint32_t& r3,
                                        uint32_t addr) {
    asm volatile("ldmatrix.sync.aligned.m8n8.x4.shared.b16 {%0,%1,%2,%3}, [%4];"
                 : "=r"(r0), "=r"(r1), "=r"(r2), "=r"(r3) : "r"(addr));
}
__device__ __forceinline__ void ldsm_x4_t(uint32_t& r0, uint32_t& r1, uint32_t& r2, uint32_t& r3,
                                          uint32_t addr) {
    asm volatile("ldmatrix.sync.aligned.m8n8.x4.trans.shared.b16 {%0,%1,%2,%3}, [%4];"
                 : "=r"(r0), "=r"(r1), "=r"(r2), "=r"(r3) : "r"(addr));
}
__device__ __forceinline__ void mma16816(float* d, const uint32_t* a, uint32_t b0, uint32_t b1) {
    asm volatile("mma.sync.aligned.m16n8k16.row.col.f32.bf16.bf16.f32 "
                 "{%0,%1,%2,%3}, {%4,%5,%6,%7}, {%8,%9}, {%0,%1,%2,%3};"
                 : "+f"(d[0]), "+f"(d[1]), "+f"(d[2]), "+f"(d[3])
                 : "r"(a[0]), "r"(a[1]), "r"(a[2]), "r"(a[3]), "r"(b0), "r"(b1));
}
__device__ __forceinline__ __nv_bfloat162 split2(float v0, float v1, __nv_bfloat162& lo) {
    __nv_bfloat16 h0 = __float2bfloat16(v0);
    __nv_bfloat16 h1 = __float2bfloat16(v1);
    lo = __nv_bfloat162(__float2bfloat16(v0 - __bfloat162float(h0)),
                        __float2bfloat16(v1 - __bfloat162float(h1)));
    return __nv_bfloat162(h0, h1);
}
#define CPA16(dst, src) \
    asm volatile("cp.async.cg.shared.global [%0], [%1], 16;" :: "r"(dst), "l"(src))
#define CPA_COMMIT() asm volatile("cp.async.commit_group;" ::: "memory")
#define CPA_WAIT1()  asm volatile("cp.async.wait_group 1;" ::: "memory")
#define CPA_WAIT0()  asm volatile("cp.async.wait_group 0;" ::: "memory")

// ====================================================================
// Multi-tensor split conversion: up to 4 fp32 [rows,1024] -> bf16 [rows,2048]
// ====================================================================
__global__ __launch_bounds__(256) void conv_split_n(
    const float* __restrict__ s0, const float* __restrict__ s1,
    const float* __restrict__ s2, const float* __restrict__ s3,
    __nv_bfloat16* __restrict__ out, int rows_each)
{
    const float* srcs[4] = {s0, s1, s2, s3};
    const float* src = srcs[blockIdx.y];
    __nv_bfloat16* dst = out + (size_t)blockIdx.y * rows_each * 2048;
    const int row = blockIdx.x;
    const int col = threadIdx.x * 4;
    float4 x = *(const float4*)(src + (size_t)row * 1024 + col);
    __nv_bfloat162 l01, l23;
    __nv_bfloat162 h01 = split2(x.x, x.y, l01);
    __nv_bfloat162 h23 = split2(x.z, x.w, l23);
    __nv_bfloat16* oh = dst + (size_t)row * 2048 + col;
    __nv_bfloat16* ol = oh + 1024;
    *(__nv_bfloat162*)(oh + 0) = h01;
    *(__nv_bfloat162*)(oh + 2) = h23;
    *(__nv_bfloat162*)(ol + 0) = l01;
    *(__nv_bfloat162*)(ol + 2) = l23;
}

// ====================================================================
// HMMA GEMM: 3-stage cp.async pipeline, one syncthreads per chunk.
// CTA 128x128, 256 thr (8 warps 4m x 2n), K' = 3072, 48 chunks of 64.
// smem: A stages [0,49152), B stages [49152, 98304).
// ====================================================================
#define GEMM_PREAMBLE()                                                              \
    const uint32_t sb = smem_to_u32(smem);                                           \
    const int tid = threadIdx.x;                                                     \
    const int lane = tid & 31;                                                       \
    const int wid = tid >> 5;                                                        \
    const int warp_m = wid >> 1;                                                     \
    const int warp_n = wid & 1;                                                      \
    float acc[2][8][4];                                                              \
    _Pragma("unroll")                                                                \
    for (int mf = 0; mf < 2; mf++)                                                   \
        _Pragma("unroll")                                                            \
        for (int nf = 0; nf < 8; nf++)                                               \
            _Pragma("unroll")                                                        \
            for (int u = 0; u < 4; u++) acc[mf][nf][u] = 0.f;                        \
    const int lrow = tid >> 1;                                                       \
    const int hsel = tid & 1;                                                        \
    const __nv_bfloat16* agbase = A2 + (size_t)(m0 + lrow) * 2048 + hsel * 32;       \
    const __nv_bfloat16* wgbase = W2 + (size_t)(n0 + lrow) * 2048 + hsel * 32;       \
    const uint32_t skey = (uint32_t)((lrow & 7) << 4);                               \
    const uint32_t srow_off = (uint32_t)(lrow * 128);                                \
    uint32_t a_base[2], a_key[2];                                                    \
    _Pragma("unroll")                                                                \
    for (int mf = 0; mf < 2; mf++) {                                                 \
        const int arow = warp_m * 32 + mf * 16 + (lane & 15);                        \
        a_base[mf] = (uint32_t)(arow * 128);                                         \
        a_key[mf] = (uint32_t)((arow & 7) << 4);                                     \
    }                                                                                \
    const uint32_t a_lo0 = (uint32_t)((lane >> 4) * 16);                             \
    uint32_t b_base[4], b_key[4];                                                    \
    _Pragma("unroll")                                                                \
    for (int p = 0; p < 4; p++) {                                                    \
        const int brow = warp_n * 64 + p * 16 + ((lane >> 4) & 1) * 8 + (lane & 7);  \
        b_base[p] = (uint32_t)(brow * 128);                                          \
        b_key[p] = (uint32_t)((brow & 7) << 4);                                      \
    }                                                                                \
    const uint32_t b_lo0 = (uint32_t)(((lane >> 3) & 1) * 16);

#define GEMM_LOAD_CHUNK(c, stg) do {                                                 \
    const int seg_ = (c) >> 4;                                                       \
    const int kc_ = ((c) & 15) << 6;                                                 \
    const __nv_bfloat16* ap_ = agbase + kc_ + (seg_ == 1 ? 1024 : 0);                \
    const __nv_bfloat16* wp_ = wgbase + kc_ + (seg_ == 2 ? 1024 : 0);                \
    const uint32_t sA_ = sb + (stg) * 16384;                                         \
    const uint32_t sB_ = sb + 49152 + (stg) * 16384;                                 \
    _Pragma("unroll")                                                                \
    for (int i = 0; i < 4; i++) {                                                    \
        const uint32_t lo_ = (uint32_t)(hsel * 64 + i * 16) ^ skey;                  \
        CPA16(sA_ + srow_off + lo_, ap_ + i * 8);                                    \
        CPA16(sB_ + srow_off + lo_, wp_ + i * 8);                                    \
    }                                                                                \
    CPA_COMMIT();                                                                    \
} while (0)

#define GEMM_MAINLOOP()                                                              \
    GEMM_LOAD_CHUNK(0, 0);                                                           \
    GEMM_LOAD_CHUNK(1, 1);                                                           \
    int st = 0;                                                                      \
    for (int c = 0; c < 48; c++) {                                                   \
        if (c < 47) { CPA_WAIT1(); } else { CPA_WAIT0(); }                           \
        __syncthreads();                                                             \
        const uint32_t sa = sb + st * 16384;                                         \
        const uint32_t sw = sb + 49152 + st * 16384;                                 \
        _Pragma("unroll")                                                            \
        for (int ks = 0; ks < 4; ks++) {                                             \
            uint32_t afrag[2][4];                                                    \
            _Pragma("unroll")                                                        \
            for (int mf = 0; mf < 2; mf++) {                                         \
                const uint32_t addr = sa + a_base[mf] +                              \
                    (((uint32_t)(ks * 32) + a_lo0) ^ a_key[mf]);                     \
                ldsm_x4(afrag[mf][0], afrag[mf][1], afrag[mf][2], afrag[mf][3], addr); \
            }                                                                        \
            _Pragma("unroll")                                                        \
            for (int p = 0; p < 4; p++) {                                            \
                const uint32_t addr = sw + b_base[p] +                               \
                    (((uint32_t)(ks * 32) + b_lo0) ^ b_key[p]);                      \
                uint32_t r0, r1, r2, r3;                                             \
                ldsm_x4(r0, r1, r2, r3, addr);                                       \
                _Pragma("unroll")                                                    \
                for (int mf = 0; mf < 2; mf++) {                                     \
                    mma16816(acc[mf][2 * p], afrag[mf], r0, r1);                     \
                    mma16816(acc[mf][2 * p + 1], afrag[mf], r2, r3);                 \
                }                                                                    \
            }                                                                        \
        }                                                                            \
        if (c + 2 < 48) {                                                            \
            int ls = st + 2; if (ls >= 3) ls -= 3;                                   \
            GEMM_LOAD_CHUNK(c + 2, ls);                                              \
        }                                                                            \
        st = (st + 1 == 3) ? 0 : st + 1;                                             \
    }

// QKV projections: one launch, z selects tensor; epilogue writes PRE-SPLIT
// bf16 hi/lo planes in [B,H,S,DK] layout. Q additionally pre-scaled by 1/8.
__global__ __launch_bounds__(256, 2) void gemm_qkv(
    const __nv_bfloat16* __restrict__ a2base, const __nv_bfloat16* __restrict__ w2base,
    const float* __restrict__ bq, const float* __restrict__ bk, const float* __restrict__ bv,
    __nv_bfloat16* __restrict__ q2, __nv_bfloat16* __restrict__ k2,
    __nv_bfloat16* __restrict__ v2)
{
    extern __shared__ char smem[];
    const int z = blockIdx.z;
    const __nv_bfloat16* A2 = a2base + (size_t)z * MTOT * 2048;
    const __nv_bfloat16* W2 = w2base + (size_t)z * D_MODEL * 2048;
    const float* bias = (z == 0) ? bq : (z == 1) ? bk : bv;
    __nv_bfloat16* Ch = (z == 0) ? q2 : (z == 1) ? k2 : v2;
    __nv_bfloat16* Cl = Ch + NTOK;
    const float scale = (z == 0) ? 0.125f : 1.0f;
    const int m0 = blockIdx.y * 128;
    const int n0 = blockIdx.x * 128;

    GEMM_PREAMBLE()
    GEMM_MAINLOOP()

    const int g = lane >> 2;
    const int tc = lane & 3;
    const int h = (n0 + warp_n * 64) >> 6;
#pragma unroll
    for (int mf = 0; mf < 2; mf++) {
#pragma unroll
        for (int nf = 0; nf < 8; nf++) {
            const int row = m0 + warp_m * 32 + mf * 16 + g;
            const int col = n0 + warp_n * 64 + nf * 8 + tc * 2;
            const int d = col & 63;
            const float b0 = bias[col];
            const float b1 = bias[col + 1];
            const int bb0 = row >> 11, s0 = row & (SEQ - 1);
            const int bb1 = (row + 8) >> 11, s1 = (row + 8) & (SEQ - 1);
            const size_t i0 = ((size_t)(bb0 * NH + h) * SEQ + s0) * DK + d;
            const size_t i1 = ((size_t)(bb1 * NH + h) * SEQ + s1) * DK + d;
            __nv_bfloat162 lo;
            __nv_bfloat162 hi = split2((acc[mf][nf][0] + b0) * scale,
                                       (acc[mf][nf][1] + b1) * scale, lo);
            *(__nv_bfloat162*)(Ch + i0) = hi;
            *(__nv_bfloat162*)(Cl + i0) = lo;
            hi = split2((acc[mf][nf][2] + b0) * scale,
                        (acc[mf][nf][3] + b1) * scale, lo);
            *(__nv_bfloat162*)(Ch + i1) = hi;
            *(__nv_bfloat162*)(Cl + i1) = lo;
        }
    }
}

// Output projection: row-major fp32 epilogue to d_out.
__global__ __launch_bounds__(256, 2) void gemm_out(
    const __nv_bfloat16* __restrict__ A2, const __nv_bfloat16* __restrict__ W2,
    const float* __restrict__ bias, float* __restrict__ C)
{
    extern __shared__ char smem[];
    const int m0 = blockIdx.y * 128;
    const int n0 = blockIdx.x * 128;

    GEMM_PREAMBLE()
    GEMM_MAINLOOP()

    const int g = lane >> 2;
    const int tc = lane & 3;
#pragma unroll
    for (int mf = 0; mf < 2; mf++) {
#pragma unroll
        for (int nf = 0; nf < 8; nf++) {
            const int row = m0 + warp_m * 32 + mf * 16 + g;
            const int col = n0 + warp_n * 64 + nf * 8 + tc * 2;
            const float b0 = bias[col];
            const float b1 = bias[col + 1];
            float2 v0 = make_float2(acc[mf][nf][0] + b0, acc[mf][nf][1] + b1);
            float2 v1 = make_float2(acc[mf][nf][2] + b0, acc[mf][nf][3] + b1);
            *(float2*)(C + (size_t)row * D_MODEL + col) = v0;
            *(float2*)(C + (size_t)(row + 8) * D_MODEL + col) = v1;
        }
    }
}

// ====================================================================
// Causal flash attention via HMMA, consuming PRE-SPLIT bf16 Q/K/V.
// CTA 256 thr (8 warps); two q-tiles (qt, 15-qt) = 34 k-tiles, uniform.
// Epilogue writes split a2 (hi|lo) directly for the output projection.
// ====================================================================
#define QH_O 0
#define QL_O 16384
#define KH_O 32768
#define KL_O 40960
#define VH_O 49152
#define VL_O 57344
#define PH_O 65536
#define PL_O 81920
#define FA_SMEM 98304

__global__ __launch_bounds__(256, 2) void flash_hmma(
    const __nv_bfloat16* __restrict__ q2, const __nv_bfloat16* __restrict__ k2,
    const __nv_bfloat16* __restrict__ v2, __nv_bfloat16* __restrict__ a2out)
{
    extern __shared__ char fsm[];
    const uint32_t sb = smem_to_u32(fsm);
    const int tid = threadIdx.x;
    const int lane = tid & 31;
    const int w = tid >> 5;
    const int bh = blockIdx.y;

    const int g = lane >> 2;
    const int tc = lane & 3;
    const int wrow = w * 16;

    const int arow = wrow + (lane & 15);
    const uint32_t a_ro = (uint32_t)(arow * 128);
    const uint32_t a_key = (uint32_t)((arow & 7) << 4);
    const uint32_t a_lo0 = (uint32_t)((lane >> 4) * 16);
    uint32_t kb_ro[4], kb_key[4];
#pragma unroll
    for (int p = 0; p < 4; p++) {
        const int brow = p * 16 + ((lane >> 4) & 1) * 8 + (lane & 7);
        kb_ro[p] = (uint32_t)(brow * 128);
        kb_key[p] = (uint32_t)((brow & 7) << 4);
    }
    const uint32_t b_lo0 = (uint32_t)(((lane >> 3) & 1) * 16);
    const uint32_t v_radd = (uint32_t)(((lane >> 3) & 1) * 8 + (lane & 7));
    const uint32_t v_key = (uint32_t)((lane & 7) << 4);
    const uint32_t v_cadd = (uint32_t)(((lane >> 4) & 1) * 16);

    for (int half = 0; half < 2; half++) {
        const int qt = (half == 0) ? (int)blockIdx.x : 15 - (int)blockIdx.x;
        const int q0 = qt * 128;
        __syncthreads();   // previous half's smem reads complete

        // ---- load pre-split Q tile (already scaled by 1/8) ----
        {
            const int row = tid >> 1;
            const int dbase = (tid & 1) * 32;
            const size_t qi = ((size_t)bh * SEQ + q0 + row) * DK + dbase;
            const uint32_t ro = (uint32_t)(row * 128);
            const uint32_t key = (uint32_t)((row & 7) << 4);
#pragma unroll
            for (int u = 0; u < 4; u++) {
                const uint32_t off = ro + (((uint32_t)(dbase * 2 + u * 16)) ^ key);
                *(uint4*)(fsm + QH_O + off) = *(const uint4*)(q2 + qi + u * 8);
                *(uint4*)(fsm + QL_O + off) = *(const uint4*)(q2 + NTOK + qi + u * 8);
            }
        }

        float mst[2] = {-1e30f, -1e30f};
        float lst[2] = {0.f, 0.f};
        float o[8][4];
#pragma unroll
        for (int nf = 0; nf < 8; nf++)
#pragma unroll
            for (int u = 0; u < 4; u++) o[nf][u] = 0.f;

        const int nkt = 2 * qt + 2;
        const int wmax = q0 + wrow + 15;

        for (int kt = 0; kt < nkt; kt++) {
            const int k0 = kt * 64;
            __syncthreads();

            // ---- load pre-split K/V tile ----
            {
                const int row = tid >> 2;
                const int dbase = (tid & 3) * 16;
                const size_t ki = ((size_t)bh * SEQ + k0 + row) * DK + dbase;
                const uint32_t ro = (uint32_t)(row * 128);
                const uint32_t key = (uint32_t)((row & 7) << 4);
#pragma unroll
                for (int u = 0; u < 2; u++) {
                    const uint32_t off = ro + (((uint32_t)(dbase * 2 + u * 16)) ^ key);
                    *(uint4*)(fsm + KH_O + off) = *(const uint4*)(k2 + ki + u * 8);
                    *(uint4*)(fsm + KL_O + off) = *(const uint4*)(k2 + NTOK + ki + u * 8);
                    *(uint4*)(fsm + VH_O + off) = *(const uint4*)(v2 + ki + u * 8);
                    *(uint4*)(fsm + VL_O + off) = *(const uint4*)(v2 + NTOK + ki + u * 8);
                }
            }
            __syncthreads();

            if (k0 <= wmax) {
                // ---- S = QK^T, 3 segments with shared B frags ----
                float s[8][4];
#pragma unroll
                for (int nf = 0; nf < 8; nf++)
#pragma unroll
                    for (int u = 0; u < 4; u++) s[nf][u] = 0.f;

#pragma unroll
                for (int ks = 0; ks < 4; ks++) {
                    uint32_t aQh[4], aQl[4];
                    const uint32_t alo = ((uint32_t)(ks * 32) + a_lo0) ^ a_key;
                    ldsm_x4(aQh[0], aQh[1], aQh[2], aQh[3], sb + QH_O + a_ro + alo);
                    ldsm_x4(aQl[0], aQl[1], aQl[2], aQl[3], sb + QL_O + a_ro + alo);
#pragma unroll
                    for (int p = 0; p < 4; p++) {
                        const uint32_t blo = ((uint32_t)(ks * 32) + b_lo0) ^ kb_key[p];
                        uint32_t r0, r1, r2, r3;
                        ldsm_x4(r0, r1, r2, r3, sb + KH_O + kb_ro[p] + blo);
                        mma16816(s[2 * p], aQh, r0, r1);
                        mma16816(s[2 * p + 1], aQh, r2, r3);
                        mma16816(s[2 * p], aQl, r0, r1);
                        mma16816(s[2 * p + 1], aQl, r2, r3);
                        ldsm_x4(r0, r1, r2, r3, sb + KL_O + kb_ro[p] + blo);
                        mma16816(s[2 * p], aQh, r0, r1);
                        mma16816(s[2 * p + 1], aQh, r2, r3);
                    }
                }

                // ---- causal mask ----
                const int r_lo = q0 + wrow + g;
                const int r_hi = r_lo + 8;
                if (k0 + 63 > q0 + wrow) {
#pragma unroll
                    for (int nf = 0; nf < 8; nf++) {
                        const int c0 = k0 + nf * 8 + tc * 2;
                        if (c0 > r_lo)     s[nf][0] = -1e30f;
                        if (c0 + 1 > r_lo) s[nf][1] = -1e30f;
                        if (c0 > r_hi)     s[nf][2] = -1e30f;
                        if (c0 + 1 > r_hi) s[nf][3] = -1e30f;
                    }
                }

                // ---- online softmax ----
#pragma unroll
                for (int h2 = 0; h2 < 2; h2++) {
                    const int i0 = h2 * 2;
                    float mloc = s[0][i0];
#pragma unroll
                    for (int nf = 0; nf < 8; nf++) {
                        mloc = fmaxf(mloc, s[nf][i0]);
                        mloc = fmaxf(mloc, s[nf][i0 + 1]);
                    }
                    mloc = fmaxf(mloc, __shfl_xor_sync(0xffffffffu, mloc, 1));
                    mloc = fmaxf(mloc, __shfl_xor_sync(0xffffffffu, mloc, 2));
                    const float mnew = fmaxf(mst[h2], mloc);
                    const float alpha = __expf(mst[h2] - mnew);
                    float psum = 0.f;
#pragma unroll
                    for (int nf = 0; nf < 8; nf++) {
                        const float p0 = __expf(s[nf][i0] - mnew);
                        const float p1 = __expf(s[nf][i0 + 1] - mnew);
                        s[nf][i0] = p0; s[nf][i0 + 1] = p1;
                        psum += p0 + p1;
                    }
                    psum += __shfl_xor_sync(0xffffffffu, psum, 1);
                    psum += __shfl_xor_sync(0xffffffffu, psum, 2);
                    lst[h2] = lst[h2] * alpha + psum;
                    mst[h2] = mnew;
#pragma unroll
                    for (int nf = 0; nf < 8; nf++) {
                        o[nf][i0] *= alpha;
                        o[nf][i0 + 1] *= alpha;
                    }
                }

                // ---- write P (hi/lo split) to smem ----
                {
                    const int prow0 = wrow + g;
                    const uint32_t pkey = (uint32_t)((g & 7) << 4);
                    const uint32_t ro0 = (uint32_t)(prow0 * 128);
                    const uint32_t ro1 = (uint32_t)((prow0 + 8) * 128);
#pragma unroll
                    for (int nf = 0; nf < 8; nf++) {
                        const uint32_t cb = (uint32_t)(nf * 16 + tc * 4) ^ pkey;
                        __nv_bfloat162 lo;
                        __nv_bfloat162 hi = split2(s[nf][0], s[nf][1], lo);
                        *(__nv_bfloat162*)(fsm + PH_O + ro0 + cb) = hi;
                        *(__nv_bfloat162*)(fsm + PL_O + ro0 + cb) = lo;
                        hi = split2(s[nf][2], s[nf][3], lo);
                        *(__nv_bfloat162*)(fsm + PH_O + ro1 + cb) = hi;
                        *(__nv_bfloat162*)(fsm + PL_O + ro1 + cb) = lo;
                    }
                }
                __syncwarp();

                // ---- O += P @ V, 3 segments with shared V frags ----
#pragma unroll
                for (int ks = 0; ks < 4; ks++) {
                    uint32_t aPh[4], aPl[4];
                    const uint32_t alo = ((uint32_t)(ks * 32) + a_lo0) ^ a_key;
                    ldsm_x4(aPh[0], aPh[1], aPh[2], aPh[3], sb + PH_O + a_ro + alo);
                    ldsm_x4(aPl[0], aPl[1], aPl[2], aPl[3], sb + PL_O + a_ro + alo);
                    const uint32_t kro = (uint32_t)(ks * 16 + v_radd) * 128;
#pragma unroll
                    for (int p = 0; p < 4; p++) {
                        const uint32_t blo = ((uint32_t)(p * 32) + v_cadd) ^ v_key;
                        uint32_t r0, r1, r2, r3;
                        ldsm_x4_t(r0, r1, r2, r3, sb + VH_O + kro + blo);
                        mma16816(o[2 * p], aPh, r0, r1);
                        mma16816(o[2 * p + 1], aPh, r2, r3);
                        mma16816(o[2 * p], aPl, r0, r1);
                        mma16816(o[2 * p + 1], aPl, r2, r3);
                        ldsm_x4_t(r0, r1, r2, r3, sb + VL_O + kro + blo);
                        mma16816(o[2 * p], aPh, r0, r1);
                        mma16816(o[2 * p + 1], aPh, r2, r3);
                    }
                }
            }
        }

        // ---- normalize + write split a2 directly ----
        const int b = bh >> 4;
        const int hh = bh & 15;
        const float inv0 = 1.0f / lst[0];
        const float inv1 = 1.0f / lst[1];
        const int r0 = q0 + wrow + g;
        const size_t m0r = ((size_t)b * SEQ + r0) * 2048;
        const size_t m1r = ((size_t)b * SEQ + r0 + 8) * 2048;
        const int colb = hh * DK + tc * 2;
#pragma unroll
        for (int nf = 0; nf < 8; nf++) {
            const int col = colb + nf * 8;
            __nv_bfloat162 lo;
            __nv_bfloat162 hi = split2(o[nf][0] * inv0, o[nf][1] * inv0, lo);
            *(__nv_bfloat162*)(a2out + m0r + col) = hi;
            *(__nv_bfloat162*)(a2out + m0r + 1024 + col) = lo;
            hi = split2(o[nf][2] * inv1, o[nf][3] * inv1, lo);
            *(__nv_bfloat162*)(a2out + m1r + col) = hi;
            *(__nv_bfloat162*)(a2out + m1r + 1024 + col) = lo;
        }
    }
}

// ====================================================================
extern "C" void kernel_launch(void* const* d_in, const int* in_sizes, int n_in,
                              void* d_out, int out_size)
{
    const float* query  = (const float*)d_in[0];
    const float* key_in = (const float*)d_in[1];
    const float* value  = (const float*)d_in[2];
    // d_in[3] = mask (causal tril, known statically -> ignored)
    const float* w_q = (const float*)d_in[4];
    const float* b_q = (const float*)d_in[5];
    const float* w_k = (const float*)d_in[6];
    const float* b_k = (const float*)d_in[7];
    const float* w_v = (const float*)d_in[8];
    const float* b_v = (const float*)d_in[9];
    const float* w_o = (const float*)d_in[10];
    const float* b_o = (const float*)d_in[11];

    __nv_bfloat16 *a2, *w2, *q2, *k2, *v2;
    cudaGetSymbolAddress((void**)&a2, g_a2);
    cudaGetSymbolAddress((void**)&w2, g_w2);
    cudaGetSymbolAddress((void**)&q2, g_q2);
    cudaGetSymbolAddress((void**)&k2, g_k2);
    cudaGetSymbolAddress((void**)&v2, g_v2);

    const int GEMM_SMEM = 98304;
    cudaFuncSetAttribute(gemm_qkv, cudaFuncAttributeMaxDynamicSharedMemorySize, GEMM_SMEM);
    cudaFuncSetAttribute(gemm_out, cudaFuncAttributeMaxDynamicSharedMemorySize, GEMM_SMEM);
    cudaFuncSetAttribute(flash_hmma, cudaFuncAttributeMaxDynamicSharedMemorySize, FA_SMEM);

    // 1) convert all 4 weight matrices (hi|lo)
    conv_split_n<<<dim3(1024, 4), 256>>>(w_q, w_k, w_v, w_o, w2, 1024);
    // 2) convert the 3 input tensors
    conv_split_n<<<dim3(4096, 3), 256>>>(query, key_in, value, nullptr, a2, 4096);
    // 3) Q/K/V projections -> pre-split bf16 planes (Q scaled 1/8)
    gemm_qkv<<<dim3(8, 32, 3), 256, GEMM_SMEM>>>(a2, w2, b_q, b_k, b_v, q2, k2, v2);
    // 4) attention -> writes split a2 slot 0 directly
    flash_hmma<<<dim3(8, BATCH * NH), 256, FA_SMEM>>>(q2, k2, v2, a2);
    // 5) output projection
    gemm_out<<<dim3(8, 32), 256, GEMM_SMEM>>>(a2, w2 + (size_t)3 * D_MODEL * 2048, b_o, (float*)d_out);
}